// round 1
// baseline (speedup 1.0000x reference)
#include <cuda_runtime.h>
#include <math.h>

#define BB 32
#define TT 2048
#define DF 128
#define NN 16
#define DY 8
#define RECSZ 256
#define NTOK 32           // tokens per phase-1 block
#define LOG2PI 1.8378770664093455

// scratch: per-token step record (64MB) + per-batch ll sums
__device__ float g_rec[(size_t)BB * TT * RECSZ];
__device__ float g_llsum[BB];

__device__ __forceinline__ float sp(float x) {
    // jax.nn.softplus = logaddexp(x, 0)
    return fmaxf(x, 0.f) + log1pf(expf(-fabsf(x)));
}
__device__ __forceinline__ float phik(float z, float k) {
    float kz = k * z;
    if (fabsf(kz) < 1e-4f) return 1.f + 0.5f * kz;
    return expm1f(kz) / kz;
}

// ---------------------------------------------------------------------------
// Phase 1: per-token projections -> step records
// grid: (BB*TT/NTOK) blocks, 256 threads. warp w handles f = w mod 8 strides,
// lane l owns token l (x row cached in 128 registers).
// record layout: [0:16) exp_z, [16:32) hx, [32:48) q, [48:176) C (d*16+n),
//                [176:184) R, [184:192) y, [192:256) zero pad
// ---------------------------------------------------------------------------
__global__ __launch_bounds__(256, 1) void phase1_kernel(
    const float* __restrict__ x, const float* __restrict__ y,
    const float* __restrict__ a_raw,
    const float* __restrict__ Wg, const float* __restrict__ bg,
    const float* __restrict__ WB, const float* __restrict__ bB,
    const float* __restrict__ WC, const float* __restrict__ bC,
    const float* __restrict__ Ws, const float* __restrict__ bs,
    const float* __restrict__ WR, const float* __restrict__ bR)
{
    __shared__ float sx[NTOK * 129];        // x tile, padded
    __shared__ float spart[8 * NN * 32];    // hx partials: [w][n][tok]
    __shared__ float ssml[25 * 33];         // gate(0), sig(1..16), R(17..24) per tok

    const int tid = threadIdx.x;
    const int w = tid >> 5, l = tid & 31;
    const size_t base = (size_t)blockIdx.x * NTOK;   // global token index base

    // load X tile (coalesced)
    for (int k = tid; k < NTOK * DF; k += 256) {
        int tok = k >> 7, g = k & 127;
        sx[tok * 129 + g] = x[(base + tok) * DF + g];
    }
    __syncthreads();

    // lane's x row into registers
    float4 xr[32];
#pragma unroll
    for (int k = 0; k < 32; k++) {
        xr[k].x = sx[l * 129 + 4 * k + 0];
        xr[k].y = sx[l * 129 + 4 * k + 1];
        xr[k].z = sx[l * 129 + 4 * k + 2];
        xr[k].w = sx[l * 129 + 4 * k + 3];
    }

    // small dots: rows 0..24 (gate, sig, R), warp w does rows w, w+8, w+16, w+24
    for (int rr = 0; rr < 4; rr++) {
        int r = w + 8 * rr;
        if (r >= 25) break;
        const float* Wrow; float bias;
        if (r == 0)       { Wrow = Wg;                  bias = bg[0]; }
        else if (r < 17)  { Wrow = Ws + (r - 1) * DF;   bias = bs[r - 1]; }
        else              { Wrow = WR + (r - 17) * DF;  bias = bR[r - 17]; }
        float acc = bias;
#pragma unroll
        for (int k = 0; k < 32; k++) {
            float4 wv = *(const float4*)(Wrow + 4 * k);
            acc += wv.x * xr[k].x + wv.y * xr[k].y + wv.z * xr[k].z + wv.w * xr[k].w;
        }
        ssml[r * 33 + l] = acc;
    }

    // hx bilinear partials: hx_raw[n] = sum_f x_f * (M_n[f,:].x + bB[n*128+f])
    for (int n = 0; n < NN; n++) {
        float accn = 0.f;
        for (int fi = 0; fi < 16; fi++) {
            int f = w + 8 * fi;
            const float* Mr = WB + ((size_t)(n * 128 + f)) * DF;
            float r = bB[n * 128 + f];
#pragma unroll
            for (int k = 0; k < 32; k++) {
                float4 wv = *(const float4*)(Mr + 4 * k);
                r += wv.x * xr[k].x + wv.y * xr[k].y + wv.z * xr[k].z + wv.w * xr[k].w;
            }
            accn += sx[l * 129 + f] * r;
        }
        spart[(w * NN + n) * 32 + l] = accn;
    }

    // Ck: warp w computes W_C rows w*16 .. w*16+15 for its lane's token,
    // vectorized stores straight to gmem record (4 at a time)
    for (int j0 = 0; j0 < 16; j0 += 4) {
        float c4[4];
#pragma unroll
        for (int q = 0; q < 4; q++) {
            int j = w * 16 + j0 + q;
            const float* Wrow = WC + (size_t)j * DF;
            float acc = bC[j];
#pragma unroll
            for (int k = 0; k < 32; k++) {
                float4 wv = *(const float4*)(Wrow + 4 * k);
                acc += wv.x * xr[k].x + wv.y * xr[k].y + wv.z * xr[k].z + wv.w * xr[k].w;
            }
            c4[q] = acc;
        }
        float4 v4 = make_float4(c4[0], c4[1], c4[2], c4[3]);
        *(float4*)(&g_rec[(base + l) * RECSZ + 48 + w * 16 + j0]) = v4;
    }
    __syncthreads();

    // combine per (tok, n)
    for (int p = tid; p < NTOK * NN; p += 256) {
        int tok = p & 31, n = p >> 5;
        float hsum = 0.f;
#pragma unroll
        for (int w2 = 0; w2 < 8; w2++) hsum += spart[(w2 * NN + n) * 32 + tok];
        float gate = ssml[0 * 33 + tok];
        float Delta = sp(gate) + 1e-6f;
        Delta = fminf(fmaxf(Delta, 1e-3f), 1.0f);
        float a = -(sp(a_raw[n]) + 1e-6f);
        float z = Delta * a;
        z = fminf(fmaxf(z, -20.f), 20.f);
        float ez  = expf(z);
        float gam = phik(z, 1.f);
        float rho = phik(z, 2.f);
        float sg = sp(ssml[(1 + n) * 33 + tok]) + 1e-6f + 1e-3f;
        size_t rb = (base + tok) * RECSZ;
        g_rec[rb + n]       = ez;
        g_rec[rb + 16 + n]  = gam * Delta * hsum;
        g_rec[rb + 32 + n]  = sg * sg * rho * Delta;
        if (n < DY) {
            float Rv = sp(ssml[(17 + n) * 33 + tok]) + 1e-6f + 1e-4f;
            g_rec[rb + 176 + n] = Rv;
            g_rec[rb + 184 + n] = y[(base + tok) * DY + n];
        }
    }
    // zero pad [192:256)
    for (int k2 = tid; k2 < NTOK * 64; k2 += 256) {
        int tok = k2 >> 6;
        g_rec[(base + tok) * RECSZ + 192 + (k2 & 63)] = 0.f;
    }
}

// ---------------------------------------------------------------------------
// Phase 2: sequential Kalman scan. 32 blocks (one per batch), 128 threads.
// ---------------------------------------------------------------------------
__global__ __launch_bounds__(128, 1) void phase2_kernel(
    const float* __restrict__ p0, float* __restrict__ out)
{
    const int b = blockIdx.x, tid = threadIdx.x;
    __shared__ float rec[RECSZ];
    __shared__ float P[16][17], Pp[16][17], IK[16][17], TM[16][17];
    __shared__ float hh[16], hp[16];
    __shared__ float A[8][26];            // [S | CP->K^T | e->v]
    __shared__ float es[8], ev[8], yps[8], Sd[8], mrow[8];
    __shared__ float piv;

    // init state
    if (tid < 16) hh[tid] = 0.f;
    {
        int e = tid;        int i = e >> 4, j = e & 15;
        P[i][j] = (i == j) ? fabsf(p0[i]) : 0.f;
        e = tid + 128;      i = e >> 4; j = e & 15;
        P[i][j] = (i == j) ? fabsf(p0[i]) : 0.f;
    }

    const float* RB = g_rec + (size_t)b * TT * RECSZ;
    float pf0 = RB[tid], pf1 = RB[tid + 128];

    float ll_s = 0.f, ll_c = 0.f;   // Kahan accumulator (tid 0 only)
    float* om = out;
    float* ov = out + (size_t)BB * TT * DY;

    for (int t = 0; t < TT; t++) {
        __syncthreads();                       // prior-step readers done
        rec[tid] = pf0; rec[tid + 128] = pf1;
        {
            size_t nb = (size_t)(t + 1 < TT ? t + 1 : t) * RECSZ;
            pf0 = RB[nb + tid]; pf1 = RB[nb + tid + 128];
        }
        __syncthreads();

        // ---- A: h_pred, P_pred
        if (tid < 16) hp[tid] = rec[tid] * hh[tid] + rec[16 + tid];
        {
            int e = tid;     int i = e >> 4, j = e & 15;
            Pp[i][j] = rec[i] * rec[j] * P[i][j] + (i == j ? rec[32 + i] : 0.f);
            e = tid + 128;   i = e >> 4; j = e & 15;
            Pp[i][j] = rec[i] * rec[j] * P[i][j] + (i == j ? rec[32 + i] : 0.f);
        }
        __syncthreads();

        // ---- B: CP into A[d][8+m]; y_pred + e by threads 0..7
        {
            int d = tid >> 4, m = tid & 15;
            float cp = 0.f;
#pragma unroll
            for (int n2 = 0; n2 < 16; n2++) cp += rec[48 + d * 16 + n2] * Pp[n2][m];
            A[d][8 + m] = cp;
        }
        if (tid < DY) {
            float yp = 0.f;
#pragma unroll
            for (int n2 = 0; n2 < 16; n2++) yp += rec[48 + tid * 16 + n2] * hp[n2];
            yps[tid] = yp;
            float ee = rec[184 + tid] - yp;
            es[tid] = ee;
            A[tid][24] = ee;
        }
        __syncthreads();

        // ---- C: S into A[d][q]
        if (tid < 64) {
            int d = tid >> 3, q = tid & 7;
            float s = (d == q) ? rec[176 + d] : 0.f;
#pragma unroll
            for (int m2 = 0; m2 < 16; m2++) s += A[d][8 + m2] * rec[48 + q * 16 + m2];
            A[d][q] = s;
            if (d == q) { Sd[d] = s; if (d == 0) piv = s; }
        }
        float ldet = 0.f;
        __syncthreads();

        // ---- D: Gauss-Jordan on [S | CP | e] (SPD, no pivoting)
        {
            int i = tid >> 4, s = tid & 15;
#pragma unroll
            for (int k = 0; k < 8; k++) {
                float p = piv;
                if (tid == 0) ldet += logf(p);
                float pinv = 1.f / p;
                if (i == k) {
                    A[k][s] *= pinv;
                    if (s < 9) A[k][s + 16] *= pinv;
                }
                if (s == k) mrow[i] = A[i][k];
                __syncthreads();
                if (i != k) {
                    float m_ = mrow[i];
                    float v1 = A[i][s] - m_ * A[k][s];
                    A[i][s] = v1;
                    if (s < 9) A[i][s + 16] -= m_ * A[k][s + 16];
                    if (k < 7 && i == k + 1 && s == k + 1) piv = v1;
                }
                __syncthreads();
            }
        }
        // now A[d][8+m] = (S^-1 CP)[d][m] = K^T ; A[d][24] = v = S^-1 e

        // ---- E: h_new, I-KC, ev
        if (tid < 16) {
            float hn = hp[tid];
#pragma unroll
            for (int d2 = 0; d2 < 8; d2++) hn += A[d2][8 + tid] * es[d2];
            hh[tid] = hn;
        }
        {
            int e = tid;     int i = e >> 4, m = e & 15;
            float v = (i == m) ? 1.f : 0.f;
#pragma unroll
            for (int d2 = 0; d2 < 8; d2++) v -= A[d2][8 + i] * rec[48 + d2 * 16 + m];
            IK[i][m] = v;
            e = tid + 128;   i = e >> 4; m = e & 15;
            float v2 = (i == m) ? 1.f : 0.f;
#pragma unroll
            for (int d2 = 0; d2 < 8; d2++) v2 -= A[d2][8 + i] * rec[48 + d2 * 16 + m];
            IK[i][m] = v2;
        }
        if (tid < DY) ev[tid] = es[tid] * A[tid][24];
        __syncthreads();

        // ---- F: TM = (I-KC) @ P_pred ; ll on thread 0
        {
            int e = tid;     int i = e >> 4, j = e & 15;
            float v = 0.f;
#pragma unroll
            for (int m2 = 0; m2 < 16; m2++) v += IK[i][m2] * Pp[m2][j];
            TM[i][j] = v;
            e = tid + 128;   i = e >> 4; j = e & 15;
            v = 0.f;
#pragma unroll
            for (int m2 = 0; m2 < 16; m2++) v += IK[i][m2] * Pp[m2][j];
            TM[i][j] = v;
        }
        if (tid == 0) {
            float quad = 0.f;
#pragma unroll
            for (int d2 = 0; d2 < 8; d2++) quad += ev[d2];
            float ll = -0.5f * (ldet + quad + (float)(DY * LOG2PI));
            // Kahan add
            float yk = ll - ll_c;
            float tk = ll_s + yk;
            ll_c = (tk - ll_s) - yk;
            ll_s = tk;
        }
        __syncthreads();

        // ---- G: P_new = TM @ (I-KC)^T + K diag(R) K^T
        {
            int e = tid;     int i = e >> 4, j = e & 15;
            float v = 0.f;
#pragma unroll
            for (int m2 = 0; m2 < 16; m2++) v += TM[i][m2] * IK[j][m2];
#pragma unroll
            for (int d2 = 0; d2 < 8; d2++) v += A[d2][8 + i] * rec[176 + d2] * A[d2][8 + j];
            P[i][j] = v;
            e = tid + 128;   i = e >> 4; j = e & 15;
            v = 0.f;
#pragma unroll
            for (int m2 = 0; m2 < 16; m2++) v += TM[i][m2] * IK[j][m2];
#pragma unroll
            for (int d2 = 0; d2 < 8; d2++) v += A[d2][8 + i] * rec[176 + d2] * A[d2][8 + j];
            P[i][j] = v;
        }

        // ---- outputs
        if (tid < DY) {
            size_t o = ((size_t)b * TT + t) * DY + tid;
            om[o] = yps[tid];
            ov[o] = Sd[tid];
        }
    }
    if (tid == 0) g_llsum[b] = ll_s;
}

// ---------------------------------------------------------------------------
// Phase 3: reduce per-batch ll sums -> nll, avg_ll
// ---------------------------------------------------------------------------
__global__ void phase3_kernel(float* __restrict__ out) {
    float v = g_llsum[threadIdx.x];
#pragma unroll
    for (int o = 16; o > 0; o >>= 1) v += __shfl_down_sync(0xffffffffu, v, o);
    if (threadIdx.x == 0) {
        size_t off = (size_t)2 * BB * TT * DY;
        out[off]     = -v / (float)BB;
        out[off + 1] =  v / (float)(BB * TT);
    }
}

extern "C" void kernel_launch(void* const* d_in, const int* in_sizes, int n_in,
                              void* d_out, int out_size) {
    const float* x_feat = (const float*)d_in[0];
    const float* y      = (const float*)d_in[1];
    const float* a_raw  = (const float*)d_in[2];
    const float* W_gate = (const float*)d_in[3];
    const float* b_gate = (const float*)d_in[4];
    const float* W_B    = (const float*)d_in[5];
    const float* b_B    = (const float*)d_in[6];
    const float* W_C    = (const float*)d_in[7];
    const float* b_C    = (const float*)d_in[8];
    const float* W_sig  = (const float*)d_in[9];
    const float* b_sig  = (const float*)d_in[10];
    const float* W_R    = (const float*)d_in[11];
    const float* b_R    = (const float*)d_in[12];
    const float* p0     = (const float*)d_in[13];
    float* out = (float*)d_out;

    phase1_kernel<<<(BB * TT) / NTOK, 256>>>(x_feat, y, a_raw, W_gate, b_gate,
                                             W_B, b_B, W_C, b_C, W_sig, b_sig,
                                             W_R, b_R);
    phase2_kernel<<<BB, 128>>>(p0, out);
    phase3_kernel<<<1, 32>>>(out);
}

// round 2
// speedup vs baseline: 1.0009x; 1.0009x over previous
#include <cuda_runtime.h>
#include <math.h>

#define BB 32
#define TT 2048
#define DF 128
#define NN 16
#define DY 8
#define RECSZ 256
#define NTOK 32           // tokens per phase-1 block
#define LOG2PI 1.8378770664093455

// scratch: per-token step record (64MB) + per-batch ll sums
__device__ float g_rec[(size_t)BB * TT * RECSZ];
__device__ float g_llsum[BB];

__device__ __forceinline__ float sp(float x) {
    // jax.nn.softplus = logaddexp(x, 0)
    return fmaxf(x, 0.f) + log1pf(expf(-fabsf(x)));
}
__device__ __forceinline__ float phik(float z, float k) {
    float kz = k * z;
    if (fabsf(kz) < 1e-4f) return 1.f + 0.5f * kz;
    return expm1f(kz) / kz;
}

// ---------------------------------------------------------------------------
// Phase 1: per-token projections -> step records
// grid: (BB*TT/NTOK) blocks, 256 threads. warp w handles f = w mod 8 strides,
// lane l owns token l (x row cached in 128 registers).
// record layout: [0:16) exp_z, [16:32) hx, [32:48) q, [48:176) C (d*16+n),
//                [176:184) R, [184:192) y, [192:256) zero pad
// ---------------------------------------------------------------------------
__global__ __launch_bounds__(256, 1) void phase1_kernel(
    const float* __restrict__ x, const float* __restrict__ y,
    const float* __restrict__ a_raw,
    const float* __restrict__ Wg, const float* __restrict__ bg,
    const float* __restrict__ WB, const float* __restrict__ bB,
    const float* __restrict__ WC, const float* __restrict__ bC,
    const float* __restrict__ Ws, const float* __restrict__ bs,
    const float* __restrict__ WR, const float* __restrict__ bR)
{
    __shared__ float sx[NTOK * 129];        // x tile, padded
    __shared__ float spart[8 * NN * 32];    // hx partials: [w][n][tok]
    __shared__ float ssml[25 * 33];         // gate(0), sig(1..16), R(17..24) per tok

    const int tid = threadIdx.x;
    const int w = tid >> 5, l = tid & 31;
    const size_t base = (size_t)blockIdx.x * NTOK;   // global token index base

    // load X tile (coalesced)
    for (int k = tid; k < NTOK * DF; k += 256) {
        int tok = k >> 7, g = k & 127;
        sx[tok * 129 + g] = x[(base + tok) * DF + g];
    }
    __syncthreads();

    // lane's x row into registers
    float4 xr[32];
#pragma unroll
    for (int k = 0; k < 32; k++) {
        xr[k].x = sx[l * 129 + 4 * k + 0];
        xr[k].y = sx[l * 129 + 4 * k + 1];
        xr[k].z = sx[l * 129 + 4 * k + 2];
        xr[k].w = sx[l * 129 + 4 * k + 3];
    }

    // small dots: rows 0..24 (gate, sig, R), warp w does rows w, w+8, w+16, w+24
    for (int rr = 0; rr < 4; rr++) {
        int r = w + 8 * rr;
        if (r >= 25) break;
        const float* Wrow; float bias;
        if (r == 0)       { Wrow = Wg;                  bias = bg[0]; }
        else if (r < 17)  { Wrow = Ws + (r - 1) * DF;   bias = bs[r - 1]; }
        else              { Wrow = WR + (r - 17) * DF;  bias = bR[r - 17]; }
        float acc = bias;
#pragma unroll
        for (int k = 0; k < 32; k++) {
            float4 wv = *(const float4*)(Wrow + 4 * k);
            acc += wv.x * xr[k].x + wv.y * xr[k].y + wv.z * xr[k].z + wv.w * xr[k].w;
        }
        ssml[r * 33 + l] = acc;
    }

    // hx bilinear partials: hx_raw[n] = sum_f x_f * (M_n[f,:].x + bB[n*128+f])
    for (int n = 0; n < NN; n++) {
        float accn = 0.f;
        for (int fi = 0; fi < 16; fi++) {
            int f = w + 8 * fi;
            const float* Mr = WB + ((size_t)(n * 128 + f)) * DF;
            float r = bB[n * 128 + f];
#pragma unroll
            for (int k = 0; k < 32; k++) {
                float4 wv = *(const float4*)(Mr + 4 * k);
                r += wv.x * xr[k].x + wv.y * xr[k].y + wv.z * xr[k].z + wv.w * xr[k].w;
            }
            accn += sx[l * 129 + f] * r;
        }
        spart[(w * NN + n) * 32 + l] = accn;
    }

    // Ck: warp w computes W_C rows w*16 .. w*16+15 for its lane's token,
    // vectorized stores straight to gmem record (4 at a time)
    for (int j0 = 0; j0 < 16; j0 += 4) {
        float c4[4];
#pragma unroll
        for (int q = 0; q < 4; q++) {
            int j = w * 16 + j0 + q;
            const float* Wrow = WC + (size_t)j * DF;
            float acc = bC[j];
#pragma unroll
            for (int k = 0; k < 32; k++) {
                float4 wv = *(const float4*)(Wrow + 4 * k);
                acc += wv.x * xr[k].x + wv.y * xr[k].y + wv.z * xr[k].z + wv.w * xr[k].w;
            }
            c4[q] = acc;
        }
        float4 v4 = make_float4(c4[0], c4[1], c4[2], c4[3]);
        *(float4*)(&g_rec[(base + l) * RECSZ + 48 + w * 16 + j0]) = v4;
    }
    __syncthreads();

    // combine per (tok, n)
    for (int p = tid; p < NTOK * NN; p += 256) {
        int tok = p & 31, n = p >> 5;
        float hsum = 0.f;
#pragma unroll
        for (int w2 = 0; w2 < 8; w2++) hsum += spart[(w2 * NN + n) * 32 + tok];
        float gate = ssml[0 * 33 + tok];
        float Delta = sp(gate) + 1e-6f;
        Delta = fminf(fmaxf(Delta, 1e-3f), 1.0f);
        float a = -(sp(a_raw[n]) + 1e-6f);
        float z = Delta * a;
        z = fminf(fmaxf(z, -20.f), 20.f);
        float ez  = expf(z);
        float gam = phik(z, 1.f);
        float rho = phik(z, 2.f);
        float sg = sp(ssml[(1 + n) * 33 + tok]) + 1e-6f + 1e-3f;
        size_t rb = (base + tok) * RECSZ;
        g_rec[rb + n]       = ez;
        g_rec[rb + 16 + n]  = gam * Delta * hsum;
        g_rec[rb + 32 + n]  = sg * sg * rho * Delta;
        if (n < DY) {
            float Rv = sp(ssml[(17 + n) * 33 + tok]) + 1e-6f + 1e-4f;
            g_rec[rb + 176 + n] = Rv;
            g_rec[rb + 184 + n] = y[(base + tok) * DY + n];
        }
    }
    // zero pad [192:256)
    for (int k2 = tid; k2 < NTOK * 64; k2 += 256) {
        int tok = k2 >> 6;
        g_rec[(base + tok) * RECSZ + 192 + (k2 & 63)] = 0.f;
    }
}

// ---------------------------------------------------------------------------
// Phase 2: sequential Kalman scan. 32 blocks (one per batch), 128 threads.
// ---------------------------------------------------------------------------
__global__ __launch_bounds__(128, 1) void phase2_kernel(
    const float* __restrict__ p0, float* __restrict__ out)
{
    const int b = blockIdx.x, tid = threadIdx.x;
    __shared__ float rec[RECSZ];
    __shared__ float P[16][17], Pp[16][17], IK[16][17], TM[16][17];
    __shared__ float hh[16], hp[16];
    __shared__ float A[8][26];            // [S | CP->K^T | e->v]
    __shared__ float es[8], ev[8], yps[8], Sd[8], mrow[8];
    __shared__ float piv;

    // init state
    if (tid < 16) hh[tid] = 0.f;
    {
        int e = tid;        int i = e >> 4, j = e & 15;
        P[i][j] = (i == j) ? fabsf(p0[i]) : 0.f;
        e = tid + 128;      i = e >> 4; j = e & 15;
        P[i][j] = (i == j) ? fabsf(p0[i]) : 0.f;
    }

    const float* RB = g_rec + (size_t)b * TT * RECSZ;
    float pf0 = RB[tid], pf1 = RB[tid + 128];

    float ll_s = 0.f, ll_c = 0.f;   // Kahan accumulator (tid 0 only)
    float* om = out;
    float* ov = out + (size_t)BB * TT * DY;

    for (int t = 0; t < TT; t++) {
        __syncthreads();                       // prior-step readers done
        rec[tid] = pf0; rec[tid + 128] = pf1;
        {
            size_t nb = (size_t)(t + 1 < TT ? t + 1 : t) * RECSZ;
            pf0 = RB[nb + tid]; pf1 = RB[nb + tid + 128];
        }
        __syncthreads();

        // ---- A: h_pred, P_pred
        if (tid < 16) hp[tid] = rec[tid] * hh[tid] + rec[16 + tid];
        {
            int e = tid;     int i = e >> 4, j = e & 15;
            Pp[i][j] = rec[i] * rec[j] * P[i][j] + (i == j ? rec[32 + i] : 0.f);
            e = tid + 128;   i = e >> 4; j = e & 15;
            Pp[i][j] = rec[i] * rec[j] * P[i][j] + (i == j ? rec[32 + i] : 0.f);
        }
        __syncthreads();

        // ---- B: CP into A[d][8+m]; y_pred + e by threads 0..7
        {
            int d = tid >> 4, m = tid & 15;
            float cp = 0.f;
#pragma unroll
            for (int n2 = 0; n2 < 16; n2++) cp += rec[48 + d * 16 + n2] * Pp[n2][m];
            A[d][8 + m] = cp;
        }
        if (tid < DY) {
            float yp = 0.f;
#pragma unroll
            for (int n2 = 0; n2 < 16; n2++) yp += rec[48 + tid * 16 + n2] * hp[n2];
            yps[tid] = yp;
            float ee = rec[184 + tid] - yp;
            es[tid] = ee;
            A[tid][24] = ee;
        }
        __syncthreads();

        // ---- C: S into A[d][q]
        if (tid < 64) {
            int d = tid >> 3, q = tid & 7;
            float s = (d == q) ? rec[176 + d] : 0.f;
#pragma unroll
            for (int m2 = 0; m2 < 16; m2++) s += A[d][8 + m2] * rec[48 + q * 16 + m2];
            A[d][q] = s;
            if (d == q) { Sd[d] = s; if (d == 0) piv = s; }
        }
        float ldet = 0.f;
        __syncthreads();

        // ---- D: Gauss-Jordan on [S | CP | e] (SPD, no pivoting)
        {
            int i = tid >> 4, s = tid & 15;
#pragma unroll
            for (int k = 0; k < 8; k++) {
                float p = piv;
                if (tid == 0) ldet += logf(p);
                float pinv = 1.f / p;
                if (i == k) {
                    A[k][s] *= pinv;
                    if (s < 9) A[k][s + 16] *= pinv;
                }
                if (s == k) mrow[i] = A[i][k];
                __syncthreads();
                if (i != k) {
                    float m_ = mrow[i];
                    float v1 = A[i][s] - m_ * A[k][s];
                    A[i][s] = v1;
                    if (s < 9) A[i][s + 16] -= m_ * A[k][s + 16];
                    if (k < 7 && i == k + 1 && s == k + 1) piv = v1;
                }
                __syncthreads();
            }
        }
        // now A[d][8+m] = (S^-1 CP)[d][m] = K^T ; A[d][24] = v = S^-1 e

        // ---- E: h_new, I-KC, ev
        if (tid < 16) {
            float hn = hp[tid];
#pragma unroll
            for (int d2 = 0; d2 < 8; d2++) hn += A[d2][8 + tid] * es[d2];
            hh[tid] = hn;
        }
        {
            int e = tid;     int i = e >> 4, m = e & 15;
            float v = (i == m) ? 1.f : 0.f;
#pragma unroll
            for (int d2 = 0; d2 < 8; d2++) v -= A[d2][8 + i] * rec[48 + d2 * 16 + m];
            IK[i][m] = v;
            e = tid + 128;   i = e >> 4; m = e & 15;
            float v2 = (i == m) ? 1.f : 0.f;
#pragma unroll
            for (int d2 = 0; d2 < 8; d2++) v2 -= A[d2][8 + i] * rec[48 + d2 * 16 + m];
            IK[i][m] = v2;
        }
        if (tid < DY) ev[tid] = es[tid] * A[tid][24];
        __syncthreads();

        // ---- F: TM = (I-KC) @ P_pred ; ll on thread 0
        {
            int e = tid;     int i = e >> 4, j = e & 15;
            float v = 0.f;
#pragma unroll
            for (int m2 = 0; m2 < 16; m2++) v += IK[i][m2] * Pp[m2][j];
            TM[i][j] = v;
            e = tid + 128;   i = e >> 4; j = e & 15;
            v = 0.f;
#pragma unroll
            for (int m2 = 0; m2 < 16; m2++) v += IK[i][m2] * Pp[m2][j];
            TM[i][j] = v;
        }
        if (tid == 0) {
            float quad = 0.f;
#pragma unroll
            for (int d2 = 0; d2 < 8; d2++) quad += ev[d2];
            float ll = -0.5f * (ldet + quad + (float)(DY * LOG2PI));
            // Kahan add
            float yk = ll - ll_c;
            float tk = ll_s + yk;
            ll_c = (tk - ll_s) - yk;
            ll_s = tk;
        }
        __syncthreads();

        // ---- G: P_new = TM @ (I-KC)^T + K diag(R) K^T
        {
            int e = tid;     int i = e >> 4, j = e & 15;
            float v = 0.f;
#pragma unroll
            for (int m2 = 0; m2 < 16; m2++) v += TM[i][m2] * IK[j][m2];
#pragma unroll
            for (int d2 = 0; d2 < 8; d2++) v += A[d2][8 + i] * rec[176 + d2] * A[d2][8 + j];
            P[i][j] = v;
            e = tid + 128;   i = e >> 4; j = e & 15;
            v = 0.f;
#pragma unroll
            for (int m2 = 0; m2 < 16; m2++) v += TM[i][m2] * IK[j][m2];
#pragma unroll
            for (int d2 = 0; d2 < 8; d2++) v += A[d2][8 + i] * rec[176 + d2] * A[d2][8 + j];
            P[i][j] = v;
        }

        // ---- outputs
        if (tid < DY) {
            size_t o = ((size_t)b * TT + t) * DY + tid;
            om[o] = yps[tid];
            ov[o] = Sd[tid];
        }
    }
    if (tid == 0) g_llsum[b] = ll_s;
}

// ---------------------------------------------------------------------------
// Phase 3: reduce per-batch ll sums -> nll, avg_ll
// ---------------------------------------------------------------------------
__global__ void phase3_kernel(float* __restrict__ out) {
    float v = g_llsum[threadIdx.x];
#pragma unroll
    for (int o = 16; o > 0; o >>= 1) v += __shfl_down_sync(0xffffffffu, v, o);
    if (threadIdx.x == 0) {
        size_t off = (size_t)2 * BB * TT * DY;
        out[off]     = -v / (float)BB;
        out[off + 1] =  v / (float)(BB * TT);
    }
}

extern "C" void kernel_launch(void* const* d_in, const int* in_sizes, int n_in,
                              void* d_out, int out_size) {
    const float* x_feat = (const float*)d_in[0];
    const float* y      = (const float*)d_in[1];
    const float* a_raw  = (const float*)d_in[2];
    const float* W_gate = (const float*)d_in[3];
    const float* b_gate = (const float*)d_in[4];
    const float* W_B    = (const float*)d_in[5];
    const float* b_B    = (const float*)d_in[6];
    const float* W_C    = (const float*)d_in[7];
    const float* b_C    = (const float*)d_in[8];
    const float* W_sig  = (const float*)d_in[9];
    const float* b_sig  = (const float*)d_in[10];
    const float* W_R    = (const float*)d_in[11];
    const float* b_R    = (const float*)d_in[12];
    const float* p0     = (const float*)d_in[13];
    float* out = (float*)d_out;

    phase1_kernel<<<(BB * TT) / NTOK, 256>>>(x_feat, y, a_raw, W_gate, b_gate,
                                             W_B, b_B, W_C, b_C, W_sig, b_sig,
                                             W_R, b_R);
    phase2_kernel<<<BB, 128>>>(p0, out);
    phase3_kernel<<<1, 32>>>(out);
}

// round 3
// speedup vs baseline: 1.1849x; 1.1838x over previous
#include <cuda_runtime.h>
#include <math.h>

#define BB 32
#define TT 2048
#define DF 128
#define NN 16
#define DY 8
#define RECSZ 256
#define NTOK 32
#define LOG2PI 1.8378770664093455f

__device__ float g_rec[(size_t)BB * TT * RECSZ];   // zero-init; pad [192,256) never written
__device__ float g_llsum[BB];

typedef unsigned long long ull;

__device__ __forceinline__ ull pk2(float a, float b) {
    ull r; asm("mov.b64 %0, {%1,%2};" : "=l"(r) : "f"(a), "f"(b)); return r;
}
__device__ __forceinline__ float sum2(ull v) {
    float a, b; asm("mov.b64 {%0,%1}, %2;" : "=f"(a), "=f"(b) : "l"(v)); return a + b;
}
__device__ __forceinline__ ull ffma2(ull a, ull b, ull c) {
    ull d; asm("fma.rn.f32x2 %0, %1, %2, %3;" : "=l"(d) : "l"(a), "l"(b), "l"(c)); return d;
}
__device__ __forceinline__ ull fadd2(ull a, ull b) {
    ull d; asm("add.rn.f32x2 %0, %1, %2;" : "=l"(d) : "l"(a), "l"(b)); return d;
}
__device__ __forceinline__ void cp16(float* s, const void* g) {
    unsigned a = (unsigned)__cvta_generic_to_shared(s);
    asm volatile("cp.async.cg.shared.global [%0], [%1], 16;" :: "r"(a), "l"(g));
}
__device__ __forceinline__ void cpcommit() { asm volatile("cp.async.commit_group;"); }
template<int N> __device__ __forceinline__ void cpwait() {
    asm volatile("cp.async.wait_group %0;" :: "n"(N));
}

__device__ __forceinline__ float sp(float x) {
    return fmaxf(x, 0.f) + log1pf(expf(-fabsf(x)));
}
__device__ __forceinline__ float phik(float z, float k) {
    float kz = k * z;
    if (fabsf(kz) < 1e-4f) return 1.f + 0.5f * kz;
    return expm1f(kz) / kz;
}

// packed dot of 128-float row (smem or gmem, 16B-aligned) with xr2 (64 packs)
__device__ __forceinline__ ull dot128(const float* __restrict__ row, const ull* xr2) {
    ull a0 = 0, a1 = 0, a2 = 0, a3 = 0;
#pragma unroll
    for (int k = 0; k < 16; k++) {
        ulonglong2 w0 = *(const ulonglong2*)(row + 8 * k);
        ulonglong2 w1 = *(const ulonglong2*)(row + 8 * k + 4);
        a0 = ffma2(w0.x, xr2[4 * k + 0], a0);
        a1 = ffma2(w0.y, xr2[4 * k + 1], a1);
        a2 = ffma2(w1.x, xr2[4 * k + 2], a2);
        a3 = ffma2(w1.y, xr2[4 * k + 3], a3);
    }
    return fadd2(fadd2(a0, a2), fadd2(a1, a3));
}

// dynamic smem layout (float offsets)
#define SM_SX    0        // 32*132
#define SM_SPART 4224     // 8*16*32
#define SM_SSML  8320     // 25*33
#define SM_W0    9152     // 16384
#define SM_W1    25536    // 16384
#define SM_TOT   41920
#define SM_BYTES (SM_TOT * 4)

__device__ __forceinline__ void stageW(const float* src, float* dst, int tid) {
    const float4* s4 = (const float4*)src;
#pragma unroll
    for (int i = 0; i < 16; i++) {
        int idx = tid + i * 256;
        cp16(dst + idx * 4, s4 + idx);
    }
}

// ---------------------------------------------------------------------------
// Phase 1: 2048 blocks x 256 threads; warp w = f-stride, lane l = token.
// record: [0:16) exp_z, [16:32) hx, [32:48) q, [48:176) C, [176:184) R, [184:192) y
// ---------------------------------------------------------------------------
__global__ __launch_bounds__(256) void phase1_kernel(
    const float* __restrict__ x, const float* __restrict__ y,
    const float* __restrict__ a_raw,
    const float* __restrict__ Wg, const float* __restrict__ bg,
    const float* __restrict__ WB, const float* __restrict__ bB,
    const float* __restrict__ WC, const float* __restrict__ bC,
    const float* __restrict__ Ws, const float* __restrict__ bs,
    const float* __restrict__ WR, const float* __restrict__ bR)
{
    extern __shared__ float dsm[];
    float* sx    = dsm + SM_SX;
    float* spart = dsm + SM_SPART;
    float* ssml  = dsm + SM_SSML;
    float* sW0   = dsm + SM_W0;
    float* sW1   = dsm + SM_W1;

    const int tid = threadIdx.x;
    const int w = tid >> 5, l = tid & 31;
    const size_t base = (size_t)blockIdx.x * NTOK;

    stageW(WB, sW0, tid);          // chunk 0 (n=0)
    cpcommit();

    for (int k = tid; k < NTOK * DF; k += 256) {
        int tok = k >> 7, g = k & 127;
        sx[tok * 132 + g] = x[(base + tok) * DF + g];
    }
    __syncthreads();

    ull xr2[64];
#pragma unroll
    for (int k = 0; k < 32; k++) {
        ulonglong2 v = *(const ulonglong2*)(sx + l * 132 + 4 * k);
        xr2[2 * k] = v.x; xr2[2 * k + 1] = v.y;
    }

    // small dots from gmem (warp-uniform LDG.128): gate(0), sig(1..16), R(17..24)
#pragma unroll
    for (int rr = 0; rr < 4; rr++) {
        int r = w + 8 * rr;
        if (r < 25) {
            const float* Wrow; float bias;
            if (r == 0)      { Wrow = Wg;                 bias = bg[0]; }
            else if (r < 17) { Wrow = Ws + (r - 1) * DF;  bias = bs[r - 1]; }
            else             { Wrow = WR + (r - 17) * DF; bias = bR[r - 17]; }
            ssml[r * 33 + l] = sum2(dot128(Wrow, xr2)) + bias;
        }
    }

    // bilinear over n, W_B staged per-n (64KB), double-buffered
    for (int n = 0; n < NN; n++) {
        float* cur = (n & 1) ? sW1 : sW0;
        float* nxt = (n & 1) ? sW0 : sW1;
        __syncthreads();                          // all done reading nxt (prev cur)
        if (n < 15) { stageW(WB + (size_t)(n + 1) * 16384, nxt, tid); cpcommit(); cpwait<1>(); }
        else        { cpwait<0>(); }
        __syncthreads();                          // cur visible to all

        ull accn2 = 0;
#pragma unroll 4
        for (int fi = 0; fi < 16; fi++) {
            int f = w + 8 * fi;
            ull rp = dot128(cur + f * 128, xr2);
            rp = fadd2(rp, pk2(bB[n * 128 + f], 0.f));
            float xf = sx[l * 132 + f];
            accn2 = ffma2(pk2(xf, xf), rp, accn2);
        }
        spart[(w * 16 + n) * 32 + l] = sum2(accn2);
    }
    __syncthreads();

    // C rows via staged W_C
    stageW(WC, sW0, tid);
    cpcommit(); cpwait<0>();
    __syncthreads();
#pragma unroll
    for (int j0 = 0; j0 < 16; j0 += 4) {
        float c4[4];
#pragma unroll
        for (int q = 0; q < 4; q++) {
            int j = w * 16 + j0 + q;
            c4[q] = sum2(dot128(sW0 + j * 128, xr2)) + bC[j];
        }
        *(float4*)(&g_rec[(base + l) * RECSZ + 48 + w * 16 + j0]) =
            make_float4(c4[0], c4[1], c4[2], c4[3]);
    }
    __syncthreads();

    // combine per (tok, n)
    for (int p = tid; p < NTOK * NN; p += 256) {
        int tok = p & 31, n = p >> 5;
        float hsum = 0.f;
#pragma unroll
        for (int w2 = 0; w2 < 8; w2++) hsum += spart[(w2 * 16 + n) * 32 + tok];
        float Delta = sp(ssml[tok]) + 1e-6f;
        Delta = fminf(fmaxf(Delta, 1e-3f), 1.0f);
        float a = -(sp(a_raw[n]) + 1e-6f);
        float z = fminf(fmaxf(Delta * a, -20.f), 20.f);
        float ez  = expf(z);
        float gam = phik(z, 1.f);
        float rho = phik(z, 2.f);
        float sg = sp(ssml[(1 + n) * 33 + tok]) + 1e-6f + 1e-3f;
        size_t rb = (base + tok) * RECSZ;
        g_rec[rb + n]      = ez;
        g_rec[rb + 16 + n] = gam * Delta * hsum;
        g_rec[rb + 32 + n] = sg * sg * rho * Delta;
        if (n < DY) {
            g_rec[rb + 176 + n] = sp(ssml[(17 + n) * 33 + tok]) + 1e-6f + 1e-4f;
            g_rec[rb + 184 + n] = y[(base + tok) * DY + n];
        }
    }
}

// ---------------------------------------------------------------------------
// Phase 2: warp-synchronous Kalman scan, 32 blocks x 32 threads (1 warp/batch)
// ---------------------------------------------------------------------------
__global__ __launch_bounds__(32, 1) void phase2_kernel(
    const float* __restrict__ p0, float* __restrict__ out)
{
    const int b = blockIdx.x, l = threadIdx.x;
    const unsigned FULL = 0xffffffffu;
    __shared__ float rec[RECSZ];
    __shared__ float sP[16 * 17], sPp[16 * 17], sT[16 * 17];
    __shared__ float sCP[8 * 17], sS[8 * 9], sK[8 * 17];
    __shared__ float se[8], sv[8], hh[16], hp[16], yps[8], Sd[8];

#pragma unroll
    for (int u = 0; u < 8; u++) {
        int e = l * 8 + u, i = e >> 4, j = e & 15;
        sP[i * 17 + j] = (i == j) ? fabsf(p0[i]) : 0.f;
    }
    if (l < 16) hh[l] = 0.f;

    const float* RB = g_rec + (size_t)b * TT * RECSZ;
    float4 pfa = *(const float4*)(RB + l * 8);
    float4 pfb = *(const float4*)(RB + l * 8 + 4);

    float ll_s = 0.f, ll_c = 0.f;
    float* om = out;
    float* ov = out + (size_t)BB * TT * DY;

    for (int t = 0; t < TT; t++) {
        __syncwarp(FULL);
        *(float4*)(rec + l * 8) = pfa;
        *(float4*)(rec + l * 8 + 4) = pfb;
        __syncwarp(FULL);
        {
            const float* nx = RB + (size_t)((t + 1 < TT) ? t + 1 : t) * RECSZ;
            pfa = *(const float4*)(nx + l * 8);
            pfb = *(const float4*)(nx + l * 8 + 4);
        }

        // h_pred, P_pred
        if (l < 16) hp[l] = rec[l] * hh[l] + rec[16 + l];
#pragma unroll
        for (int u = 0; u < 8; u++) {
            int e = l * 8 + u, i = e >> 4, j = e & 15;
            sPp[i * 17 + j] = rec[i] * rec[j] * sP[i * 17 + j] + ((i == j) ? rec[32 + i] : 0.f);
        }
        __syncwarp(FULL);

        // CP (4 per lane) + y_pred/e
        {
            int d = l >> 2, j0 = (l & 3) * 4;
            float C[16];
#pragma unroll
            for (int n = 0; n < 16; n++) C[n] = rec[48 + d * 16 + n];
#pragma unroll
            for (int jj = 0; jj < 4; jj++) {
                float s0 = 0.f, s1 = 0.f;
#pragma unroll
                for (int n = 0; n < 16; n += 2) {
                    s0 += C[n]     * sPp[n * 17 + j0 + jj];
                    s1 += C[n + 1] * sPp[(n + 1) * 17 + j0 + jj];
                }
                sCP[d * 17 + j0 + jj] = s0 + s1;
            }
            if ((l & 3) == 0) {
                float s0 = 0.f, s1 = 0.f;
#pragma unroll
                for (int n = 0; n < 16; n += 2) { s0 += C[n] * hp[n]; s1 += C[n + 1] * hp[n + 1]; }
                float yp = s0 + s1;
                yps[d] = yp;
                se[d] = rec[184 + d] - yp;
            }
        }
        __syncwarp(FULL);

        // S (2 per lane)
#pragma unroll
        for (int u = 0; u < 2; u++) {
            int s = l * 2 + u, d = s >> 3, q = s & 7;
            float a0 = 0.f, a1 = 0.f;
#pragma unroll
            for (int m = 0; m < 16; m += 2) {
                a0 += sCP[d * 17 + m]     * rec[48 + q * 16 + m];
                a1 += sCP[d * 17 + m + 1] * rec[48 + q * 16 + m + 1];
            }
            float vv = a0 + a1 + ((d == q) ? rec[176 + d] : 0.f);
            sS[d * 9 + q] = vv;
            if (d == q) Sd[d] = vv;
        }
        __syncwarp(FULL);

        // Gauss-Jordan on [S | CP | e]: lane = column, rows in registers
        float r[8];
#pragma unroll
        for (int d = 0; d < 8; d++) {
            float v;
            if (l < 8)        v = sS[d * 9 + l];
            else if (l < 24)  v = sCP[d * 17 + (l - 8)];
            else if (l == 24) v = se[d];
            else              v = 0.f;
            r[d] = v;
        }
        float ldet = 0.f;
#pragma unroll
        for (int k = 0; k < 8; k++) {
            float piv = __shfl_sync(FULL, r[k], k);
            ldet += logf(piv);
            float pinv = 1.f / piv;
            r[k] *= pinv;
#pragma unroll
            for (int i = 0; i < 8; i++) if (i != k) {
                float m = __shfl_sync(FULL, r[i], k);
                r[i] -= m * r[k];
            }
        }
        // r now: cols 8..23 = K'[d][m] (= S^-1 CP), col 24 = v
        if (l >= 8 && l < 24) {
            int m = l - 8;
#pragma unroll
            for (int d = 0; d < 8; d++) sK[d * 17 + m] = r[d];
        }
        if (l == 24) {
#pragma unroll
            for (int d = 0; d < 8; d++) sv[d] = r[d];
        }
        __syncwarp(FULL);

        // h_new, ll
        if (l < 16) {
            float hn = hp[l];
#pragma unroll
            for (int d = 0; d < 8; d++) hn += sK[d * 17 + l] * se[d];
            hh[l] = hn;
        }
        if (l == 0) {
            float quad = 0.f;
#pragma unroll
            for (int d = 0; d < 8; d++) quad += se[d] * sv[d];
            float ll = -0.5f * (ldet + quad + (float)DY * LOG2PI);
            float yk = ll - ll_c, tk = ll_s + yk;
            ll_c = (tk - ll_s) - yk; ll_s = tk;
        }

        // P_new = Pp - K'^T(CP) ; then symmetrize
#pragma unroll
        for (int u = 0; u < 8; u++) {
            int e = l * 8 + u, i = e >> 4, j = e & 15;
            float v = sPp[i * 17 + j];
#pragma unroll
            for (int d = 0; d < 8; d++) v -= sK[d * 17 + i] * sCP[d * 17 + j];
            sT[i * 17 + j] = v;
        }
        __syncwarp(FULL);
#pragma unroll
        for (int u = 0; u < 8; u++) {
            int e = l * 8 + u, i = e >> 4, j = e & 15;
            sP[i * 17 + j] = 0.5f * (sT[i * 17 + j] + sT[j * 17 + i]);
        }

        if (l < DY) {
            size_t o = ((size_t)b * TT + t) * DY + l;
            om[o] = yps[l];
            ov[o] = Sd[l];
        }
    }
    if (l == 0) g_llsum[b] = ll_s;
}

__global__ void phase3_kernel(float* __restrict__ out) {
    float v = g_llsum[threadIdx.x];
#pragma unroll
    for (int o = 16; o > 0; o >>= 1) v += __shfl_down_sync(0xffffffffu, v, o);
    if (threadIdx.x == 0) {
        size_t off = (size_t)2 * BB * TT * DY;
        out[off]     = -v / (float)BB;
        out[off + 1] =  v / (float)(BB * TT);
    }
}

extern "C" void kernel_launch(void* const* d_in, const int* in_sizes, int n_in,
                              void* d_out, int out_size) {
    const float* x_feat = (const float*)d_in[0];
    const float* y      = (const float*)d_in[1];
    const float* a_raw  = (const float*)d_in[2];
    const float* W_gate = (const float*)d_in[3];
    const float* b_gate = (const float*)d_in[4];
    const float* W_B    = (const float*)d_in[5];
    const float* b_B    = (const float*)d_in[6];
    const float* W_C    = (const float*)d_in[7];
    const float* b_C    = (const float*)d_in[8];
    const float* W_sig  = (const float*)d_in[9];
    const float* b_sig  = (const float*)d_in[10];
    const float* W_R    = (const float*)d_in[11];
    const float* b_R    = (const float*)d_in[12];
    const float* p0     = (const float*)d_in[13];
    float* out = (float*)d_out;

    cudaFuncSetAttribute(phase1_kernel,
                         cudaFuncAttributeMaxDynamicSharedMemorySize, SM_BYTES);
    phase1_kernel<<<(BB * TT) / NTOK, 256, SM_BYTES>>>(
        x_feat, y, a_raw, W_gate, b_gate, W_B, b_B, W_C, b_C,
        W_sig, b_sig, W_R, b_R);
    phase2_kernel<<<BB, 32>>>(p0, out);
    phase3_kernel<<<1, 32>>>(out);
}

// round 5
// speedup vs baseline: 2.0458x; 1.7265x over previous
#include <cuda_runtime.h>
#include <math.h>

#define BB 32
#define TT 2048
#define DF 128
#define NN 16
#define DY 8
#define RECSZ 256
#define NTOK 32
#define LOG2PI 1.8378770664093455f

__device__ float g_rec[(size_t)BB * TT * RECSZ];   // zero-init; pad [192,256) never written
__device__ float g_llsum[BB];

typedef unsigned long long ull;

__device__ __forceinline__ ull pk2(float a, float b) {
    ull r; asm("mov.b64 %0, {%1,%2};" : "=l"(r) : "f"(a), "f"(b)); return r;
}
__device__ __forceinline__ float sum2(ull v) {
    float a, b; asm("mov.b64 {%0,%1}, %2;" : "=f"(a), "=f"(b) : "l"(v)); return a + b;
}
__device__ __forceinline__ ull ffma2(ull a, ull b, ull c) {
    ull d; asm("fma.rn.f32x2 %0, %1, %2, %3;" : "=l"(d) : "l"(a), "l"(b), "l"(c)); return d;
}
__device__ __forceinline__ ull fadd2(ull a, ull b) {
    ull d; asm("add.rn.f32x2 %0, %1, %2;" : "=l"(d) : "l"(a), "l"(b)); return d;
}
__device__ __forceinline__ float frcp(float x) {
    float r; asm("rcp.approx.f32 %0, %1;" : "=f"(r) : "f"(x)); return r;
}
__device__ __forceinline__ void cp16(float* s, const void* g) {
    unsigned a = (unsigned)__cvta_generic_to_shared(s);
    asm volatile("cp.async.cg.shared.global [%0], [%1], 16;" :: "r"(a), "l"(g));
}
__device__ __forceinline__ void cpcommit() { asm volatile("cp.async.commit_group;"); }
template<int N> __device__ __forceinline__ void cpwait() {
    asm volatile("cp.async.wait_group %0;" :: "n"(N));
}

__device__ __forceinline__ float sp(float x) {
    return fmaxf(x, 0.f) + log1pf(expf(-fabsf(x)));
}
__device__ __forceinline__ float phik(float z, float k) {
    float kz = k * z;
    if (fabsf(kz) < 1e-4f) return 1.f + 0.5f * kz;
    return expm1f(kz) / kz;
}

// packed dot of 64-float half-row with xr2 (32 packs)
__device__ __forceinline__ ull dot64(const float* __restrict__ row, const ull* xr2) {
    ull a0 = 0, a1 = 0, a2 = 0, a3 = 0;
#pragma unroll
    for (int k = 0; k < 8; k++) {
        ulonglong2 w0 = *(const ulonglong2*)(row + 8 * k);
        ulonglong2 w1 = *(const ulonglong2*)(row + 8 * k + 4);
        a0 = ffma2(w0.x, xr2[4 * k + 0], a0);
        a1 = ffma2(w0.y, xr2[4 * k + 1], a1);
        a2 = ffma2(w1.x, xr2[4 * k + 2], a2);
        a3 = ffma2(w1.y, xr2[4 * k + 3], a3);
    }
    return fadd2(fadd2(a0, a2), fadd2(a1, a3));
}

// phase1 dynamic smem layout (float offsets)
#define SM_SX    0        // 32*132 = 4224
#define SM_SPART 4224     // 16*16*32 = 8192 (also reused: [128 j][2 half][32 tok])
#define SM_SSML  12416    // 25*66 = 1650 (pad to 1664)
#define SM_W0    14080    // 16384
#define SM_W1    30464    // 16384
#define SM_TOT   46848
#define SM_BYTES (SM_TOT * 4)

__device__ __forceinline__ void stageW512(const float* src, float* dst, int tid) {
    const float4* s4 = (const float4*)src;
#pragma unroll
    for (int i = 0; i < 8; i++) {
        int idx = tid + i * 512;
        cp16(dst + idx * 4, s4 + idx);
    }
}

// ---------------------------------------------------------------------------
// Phase 1: 2048 blocks x 512 threads. warp = (wf = warp&7 f-stride, half = warp>>3
// owning 64 of 128 columns), lane = token. Partial dots combined via smem.
// record: [0:16) exp_z, [16:32) hx, [32:48) q, [48:176) C, [176:184) R, [184:192) y
// ---------------------------------------------------------------------------
__global__ __launch_bounds__(512, 1) void phase1_kernel(
    const float* __restrict__ x, const float* __restrict__ y,
    const float* __restrict__ a_raw,
    const float* __restrict__ Wg, const float* __restrict__ bg,
    const float* __restrict__ WB, const float* __restrict__ bB,
    const float* __restrict__ WC, const float* __restrict__ bC,
    const float* __restrict__ Ws, const float* __restrict__ bs,
    const float* __restrict__ WR, const float* __restrict__ bR)
{
    extern __shared__ float dsm[];
    float* sx    = dsm + SM_SX;
    float* spart = dsm + SM_SPART;
    float* ssml  = dsm + SM_SSML;
    float* sW0   = dsm + SM_W0;
    float* sW1   = dsm + SM_W1;

    const int tid = threadIdx.x;
    const int warp = tid >> 5, l = tid & 31;
    const int wf = warp & 7, half = warp >> 3;
    const int co = half * 64;                      // column offset for this half
    const size_t base = (size_t)blockIdx.x * NTOK;

    stageW512(WB, sW0, tid);       // chunk n=0
    cpcommit();

    for (int k = tid; k < NTOK * DF; k += 512) {
        int tok = k >> 7, g = k & 127;
        sx[tok * 132 + g] = x[(base + tok) * DF + g];
    }
    __syncthreads();

    // lane's half x-row into 32 packs
    ull xr2[32];
#pragma unroll
    for (int k = 0; k < 16; k++) {
        ulonglong2 v = *(const ulonglong2*)(sx + l * 132 + co + 4 * k);
        xr2[2 * k] = v.x; xr2[2 * k + 1] = v.y;
    }

    // small dots (partial over half cols): gate(0), sig(1..16), R(17..24)
#pragma unroll
    for (int rr = 0; rr < 4; rr++) {
        int r = wf + 8 * rr;
        if (r < 25) {
            const float* Wrow; float bias;
            if (r == 0)      { Wrow = Wg;                 bias = bg[0]; }
            else if (r < 17) { Wrow = Ws + (r - 1) * DF;  bias = bs[r - 1]; }
            else             { Wrow = WR + (r - 17) * DF; bias = bR[r - 17]; }
            float v = sum2(dot64(Wrow + co, xr2));
            if (half == 0) v += bias;
            ssml[r * 66 + half * 33 + l] = v;
        }
    }

    // bilinear over n chunks (64KB each), double-buffered
    for (int n = 0; n < NN; n++) {
        float* cur = (n & 1) ? sW1 : sW0;
        float* nxt = (n & 1) ? sW0 : sW1;
        __syncthreads();
        if (n < 15) { stageW512(WB + (size_t)(n + 1) * 16384, nxt, tid); cpcommit(); cpwait<1>(); }
        else        { cpwait<0>(); }
        __syncthreads();

        ull accn2 = 0;
        float bacc = 0.f;
#pragma unroll 4
        for (int fi = 0; fi < 16; fi++) {
            int f = wf + 8 * fi;
            ull rp = dot64(cur + f * 128 + co, xr2);
            float xf = sx[l * 132 + f];
            accn2 = ffma2(pk2(xf, xf), rp, accn2);
            if (half == 0) bacc += xf * bB[n * 128 + f];
        }
        spart[warp * 512 + n * 32 + l] = sum2(accn2) + bacc;
    }
    __syncthreads();

    // start staging W_C (sW0 free), overlap with hx combine
    stageW512(WC, sW0, tid);
    cpcommit();

    // hx combine + scalar record fields: 512 threads = 32 tok x 16 n exactly
    {
        int tok = tid & 31, n = tid >> 5;
        float hsum = 0.f;
#pragma unroll
        for (int w2 = 0; w2 < 16; w2++) hsum += spart[w2 * 512 + n * 32 + tok];
        float gate = ssml[tok] + ssml[33 + tok];
        float Delta = sp(gate) + 1e-6f;
        Delta = fminf(fmaxf(Delta, 1e-3f), 1.0f);
        float a = -(sp(a_raw[n]) + 1e-6f);
        float z = fminf(fmaxf(Delta * a, -20.f), 20.f);
        float ez  = expf(z);
        float gam = phik(z, 1.f);
        float rho = phik(z, 2.f);
        float sg = sp(ssml[(1 + n) * 66 + tok] + ssml[(1 + n) * 66 + 33 + tok]) + 1e-6f + 1e-3f;
        size_t rb = (base + tok) * RECSZ;
        g_rec[rb + n]      = ez;
        g_rec[rb + 16 + n] = gam * Delta * hsum;
        g_rec[rb + 32 + n] = sg * sg * rho * Delta;
        if (n < DY) {
            g_rec[rb + 176 + n] = sp(ssml[(17 + n) * 66 + tok] + ssml[(17 + n) * 66 + 33 + tok])
                                  + 1e-6f + 1e-4f;
            g_rec[rb + 184 + n] = y[(base + tok) * DY + n];
        }
    }
    cpwait<0>();
    __syncthreads();      // WC staged AND spart readers done

    // C partial dots: warp (wf, half) does rows wf*16..wf*16+15 (half cols), lane=token
#pragma unroll 4
    for (int jj = 0; jj < 16; jj++) {
        int j = wf * 16 + jj;
        spart[j * 64 + half * 32 + l] = sum2(dot64(sW0 + j * 128 + co, xr2));
    }
    __syncthreads();

    // C combine: 1024 float4 outputs (32 tok x 32 j-quads)
    for (int idx = tid; idx < 1024; idx += 512) {
        int tok = idx & 31, j4 = (idx >> 5) * 4;
        float4 v;
        v.x = spart[(j4 + 0) * 64 + tok] + spart[(j4 + 0) * 64 + 32 + tok] + bC[j4 + 0];
        v.y = spart[(j4 + 1) * 64 + tok] + spart[(j4 + 1) * 64 + 32 + tok] + bC[j4 + 1];
        v.z = spart[(j4 + 2) * 64 + tok] + spart[(j4 + 2) * 64 + 32 + tok] + bC[j4 + 2];
        v.w = spart[(j4 + 3) * 64 + tok] + spart[(j4 + 3) * 64 + 32 + tok] + bC[j4 + 3];
        *(float4*)(&g_rec[(base + tok) * RECSZ + 48 + j4]) = v;
    }
}

// ---------------------------------------------------------------------------
// Phase 2: warp-synchronous Kalman scan, 32 blocks x 32 threads.
// Vectorized smem layouts (strides 20/12), rcp.approx pivots, logf(prod) once.
// ---------------------------------------------------------------------------
__global__ __launch_bounds__(32, 1) void phase2_kernel(
    const float* __restrict__ p0, float* __restrict__ out)
{
    const int b = blockIdx.x, l = threadIdx.x;
    const unsigned FULL = 0xffffffffu;
    __shared__ __align__(16) float rec[RECSZ];
    __shared__ __align__(16) float sP[320], sPp[320], sT[320];
    __shared__ __align__(16) float sCP[160], sCPT[192], sKT[192];
    __shared__ __align__(16) float sS[72], se[8], hh[16], hp[16], yps[8], Sd[8];

    const int i2 = l >> 1, jb = (l & 1) * 8;       // (row, col-block) for 16x16 work
    const int d4 = l >> 2, j04 = (l & 3) * 4;      // for CP stage

    // init
#pragma unroll
    for (int u = 0; u < 8; u++)
        sP[i2 * 20 + jb + u] = (i2 == jb + u) ? fabsf(p0[i2]) : 0.f;
    if (l < 16) hh[l] = 0.f;

    const float* RB = g_rec + (size_t)b * TT * RECSZ;
    float4 pfa = *(const float4*)(RB + l * 8);
    float4 pfb = *(const float4*)(RB + l * 8 + 4);

    float ll_s = 0.f, ll_c = 0.f;                  // lane 24 only
    float* om = out;
    float* ov = out + (size_t)BB * TT * DY;

    for (int t = 0; t < TT; t++) {
        *(float4*)(rec + l * 8) = pfa;
        *(float4*)(rec + l * 8 + 4) = pfb;
        __syncwarp(FULL);
        {
            const float* nx = RB + (size_t)((t + 1 < TT) ? t + 1 : t) * RECSZ;
            pfa = *(const float4*)(nx + l * 8);
            pfb = *(const float4*)(nx + l * 8 + 4);
        }

        // ---- Pp + h_pred
        if (l < 16) hp[l] = rec[l] * hh[l] + rec[16 + l];
        {
            float ezi = rec[i2], qi = rec[32 + i2];
            float4 e0 = *(const float4*)&rec[jb];
            float4 e1 = *(const float4*)&rec[jb + 4];
            float4 pa = *(const float4*)&sP[i2 * 20 + jb];
            float4 pb = *(const float4*)&sP[i2 * 20 + jb + 4];
            float o[8];
            o[0] = ezi * e0.x * pa.x; o[1] = ezi * e0.y * pa.y;
            o[2] = ezi * e0.z * pa.z; o[3] = ezi * e0.w * pa.w;
            o[4] = ezi * e1.x * pb.x; o[5] = ezi * e1.y * pb.y;
            o[6] = ezi * e1.z * pb.z; o[7] = ezi * e1.w * pb.w;
#pragma unroll
            for (int u = 0; u < 8; u++) if (i2 == jb + u) o[u] += qi;
            *(float4*)&sPp[i2 * 20 + jb]     = make_float4(o[0], o[1], o[2], o[3]);
            *(float4*)&sPp[i2 * 20 + jb + 4] = make_float4(o[4], o[5], o[6], o[7]);
        }
        __syncwarp(FULL);

        // ---- CP (4 per lane) + y_pred/e
        {
            const float* Crow = rec + 48 + d4 * 16;
            float4 ca = *(const float4*)(Crow);
            float4 cb = *(const float4*)(Crow + 4);
            float4 cc = *(const float4*)(Crow + 8);
            float4 cd = *(const float4*)(Crow + 12);
            float C[16] = {ca.x,ca.y,ca.z,ca.w, cb.x,cb.y,cb.z,cb.w,
                           cc.x,cc.y,cc.z,cc.w, cd.x,cd.y,cd.z,cd.w};
            float a0 = 0.f, a1 = 0.f, a2 = 0.f, a3 = 0.f;
#pragma unroll
            for (int n = 0; n < 16; n++) {
                float4 pv = *(const float4*)&sPp[n * 20 + j04];
                a0 += C[n] * pv.x; a1 += C[n] * pv.y;
                a2 += C[n] * pv.z; a3 += C[n] * pv.w;
            }
            *(float4*)&sCP[d4 * 20 + j04] = make_float4(a0, a1, a2, a3);
            sCPT[(j04 + 0) * 12 + d4] = a0;
            sCPT[(j04 + 1) * 12 + d4] = a1;
            sCPT[(j04 + 2) * 12 + d4] = a2;
            sCPT[(j04 + 3) * 12 + d4] = a3;
            if ((l & 3) == 0) {
                float yp = 0.f;
#pragma unroll
                for (int n = 0; n < 16; n++) yp += C[n] * hp[n];
                yps[d4] = yp;
                se[d4] = rec[184 + d4] - yp;
            }
        }
        __syncwarp(FULL);

        // ---- S (2 per lane) via f32x2
        {
            int d = d4, q0 = (l & 3) * 2;
            ulonglong2 g0 = *(const ulonglong2*)&sCP[d * 20];
            ulonglong2 g1 = *(const ulonglong2*)&sCP[d * 20 + 4];
            ulonglong2 g2 = *(const ulonglong2*)&sCP[d * 20 + 8];
            ulonglong2 g3 = *(const ulonglong2*)&sCP[d * 20 + 12];
#pragma unroll
            for (int qq = 0; qq < 2; qq++) {
                int q = q0 + qq;
                ulonglong2 c0 = *(const ulonglong2*)&rec[48 + q * 16];
                ulonglong2 c1 = *(const ulonglong2*)&rec[48 + q * 16 + 4];
                ulonglong2 c2 = *(const ulonglong2*)&rec[48 + q * 16 + 8];
                ulonglong2 c3 = *(const ulonglong2*)&rec[48 + q * 16 + 12];
                ull x0 = ffma2(g0.x, c0.x, ffma2(g0.y, c0.y, 0));
                ull x1 = ffma2(g1.x, c1.x, ffma2(g1.y, c1.y, 0));
                ull x2 = ffma2(g2.x, c2.x, ffma2(g2.y, c2.y, 0));
                ull x3 = ffma2(g3.x, c3.x, ffma2(g3.y, c3.y, 0));
                float s = sum2(fadd2(fadd2(x0, x1), fadd2(x2, x3)));
                if (d == q) { s += rec[176 + d]; Sd[d] = s; }
                sS[d * 9 + q] = s;
            }
        }
        __syncwarp(FULL);

        // ---- Gauss-Jordan on [S | CP | e]: lane = column, rows in regs
        float r[8];
        if (l < 8) {
#pragma unroll
            for (int d = 0; d < 8; d++) r[d] = sS[d * 9 + l];
        } else if (l < 24) {
            int m = l - 8;
#pragma unroll
            for (int d = 0; d < 8; d++) r[d] = sCP[d * 20 + m];
        } else if (l == 24) {
#pragma unroll
            for (int d = 0; d < 8; d++) r[d] = se[d];
        } else {
#pragma unroll
            for (int d = 0; d < 8; d++) r[d] = 0.f;
        }
        float pprod = 1.f;
#pragma unroll
        for (int k = 0; k < 8; k++) {
            float piv = __shfl_sync(FULL, r[k], k);
            pprod *= piv;
            float pinv = frcp(piv);
            r[k] *= pinv;
#pragma unroll
            for (int i = 0; i < 8; i++) if (i != k) {
                float m = __shfl_sync(FULL, r[i], k);
                r[i] -= m * r[k];
            }
        }
        if (l >= 8 && l < 24) {
            int m = l - 8;
#pragma unroll
            for (int d = 0; d < 8; d++) sKT[m * 12 + d] = r[d];
        }
        __syncwarp(FULL);

        // ---- h_new (lanes<16), ll (lane 24), outputs (lanes<8)
        if (l < 16) {
            ulonglong2 k0 = *(const ulonglong2*)&sKT[l * 12];
            ulonglong2 k1 = *(const ulonglong2*)&sKT[l * 12 + 4];
            ulonglong2 e0 = *(const ulonglong2*)&se[0];
            ulonglong2 e1 = *(const ulonglong2*)&se[4];
            ull acc = ffma2(k0.x, e0.x, ffma2(k0.y, e0.y,
                      ffma2(k1.x, e1.x, ffma2(k1.y, e1.y, 0))));
            hh[l] = hp[l] + sum2(acc);
        }
        if (l == 24) {
            float quad = 0.f;
#pragma unroll
            for (int d = 0; d < 8; d++) quad += se[d] * r[d];
            float ll = -0.5f * (logf(pprod) + quad + (float)DY * LOG2PI);
            float yk = ll - ll_c, tk = ll_s + yk;
            ll_c = (tk - ll_s) - yk; ll_s = tk;
        }
        if (l < DY) {
            size_t o = ((size_t)b * TT + t) * DY + l;
            om[o] = yps[l];
            ov[o] = Sd[l];
        }

        // ---- P_new = Pp - K'^T CP  (row i2, cols jb..jb+7)
        {
            ulonglong2 K0 = *(const ulonglong2*)&sKT[i2 * 12];
            ulonglong2 K1 = *(const ulonglong2*)&sKT[i2 * 12 + 4];
            float4 p0v = *(const float4*)&sPp[i2 * 20 + jb];
            float4 p1v = *(const float4*)&sPp[i2 * 20 + jb + 4];
            float pp[8] = {p0v.x,p0v.y,p0v.z,p0v.w, p1v.x,p1v.y,p1v.z,p1v.w};
            float o[8];
#pragma unroll
            for (int u = 0; u < 8; u++) {
                int j = jb + u;
                ulonglong2 c0 = *(const ulonglong2*)&sCPT[j * 12];
                ulonglong2 c1 = *(const ulonglong2*)&sCPT[j * 12 + 4];
                ull acc = ffma2(K0.x, c0.x, ffma2(K0.y, c0.y,
                          ffma2(K1.x, c1.x, ffma2(K1.y, c1.y, 0))));
                o[u] = pp[u] - sum2(acc);
            }
            *(float4*)&sT[i2 * 20 + jb]     = make_float4(o[0], o[1], o[2], o[3]);
            *(float4*)&sT[i2 * 20 + jb + 4] = make_float4(o[4], o[5], o[6], o[7]);
        }
        __syncwarp(FULL);

        // ---- symmetrize into sP
        {
            float4 t0 = *(const float4*)&sT[i2 * 20 + jb];
            float4 t1 = *(const float4*)&sT[i2 * 20 + jb + 4];
            float tv[8] = {t0.x,t0.y,t0.z,t0.w, t1.x,t1.y,t1.z,t1.w};
            float o[8];
#pragma unroll
            for (int u = 0; u < 8; u++)
                o[u] = 0.5f * (tv[u] + sT[(jb + u) * 20 + i2]);
            *(float4*)&sP[i2 * 20 + jb]     = make_float4(o[0], o[1], o[2], o[3]);
            *(float4*)&sP[i2 * 20 + jb + 4] = make_float4(o[4], o[5], o[6], o[7]);
        }
        __syncwarp(FULL);
    }
    if (l == 24) g_llsum[b] = ll_s;
}

__global__ void phase3_kernel(float* __restrict__ out) {
    float v = g_llsum[threadIdx.x];
#pragma unroll
    for (int o = 16; o > 0; o >>= 1) v += __shfl_down_sync(0xffffffffu, v, o);
    if (threadIdx.x == 0) {
        size_t off = (size_t)2 * BB * TT * DY;
        out[off]     = -v / (float)BB;
        out[off + 1] =  v / (float)(BB * TT);
    }
}

extern "C" void kernel_launch(void* const* d_in, const int* in_sizes, int n_in,
                              void* d_out, int out_size) {
    const float* x_feat = (const float*)d_in[0];
    const float* y      = (const float*)d_in[1];
    const float* a_raw  = (const float*)d_in[2];
    const float* W_gate = (const float*)d_in[3];
    const float* b_gate = (const float*)d_in[4];
    const float* W_B    = (const float*)d_in[5];
    const float* b_B    = (const float*)d_in[6];
    const float* W_C    = (const float*)d_in[7];
    const float* b_C    = (const float*)d_in[8];
    const float* W_sig  = (const float*)d_in[9];
    const float* b_sig  = (const float*)d_in[10];
    const float* W_R    = (const float*)d_in[11];
    const float* b_R    = (const float*)d_in[12];
    const float* p0     = (const float*)d_in[13];
    float* out = (float*)d_out;

    cudaFuncSetAttribute(phase1_kernel,
                         cudaFuncAttributeMaxDynamicSharedMemorySize, SM_BYTES);
    phase1_kernel<<<(BB * TT) / NTOK, 512, SM_BYTES>>>(
        x_feat, y, a_raw, W_gate, b_gate, W_B, b_B, W_C, b_C,
        W_sig, b_sig, W_R, b_R);
    phase2_kernel<<<BB, 32>>>(p0, out);
    phase3_kernel<<<1, 32>>>(out);
}

// round 6
// speedup vs baseline: 3.1445x; 1.5371x over previous
#include <cuda_runtime.h>
#include <math.h>

#define BB 32
#define TT 2048
#define DF 128
#define NN 16
#define DY 8
#define RECSZ 256
#define NTOK 32
#define NCHUNK 64                 // TT / NTOK
#define LOG2PI 1.8378770664093455f

__device__ float g_rec[(size_t)BB * TT * RECSZ];   // zero-init; pad [192,256) never written
__device__ float g_llsum[BB];
__device__ int   g_flag[BB * NCHUNK];              // memset to 0 each launch

typedef unsigned long long ull;

__device__ __forceinline__ ull pk2(float a, float b) {
    ull r; asm("mov.b64 %0, {%1,%2};" : "=l"(r) : "f"(a), "f"(b)); return r;
}
__device__ __forceinline__ float sum2(ull v) {
    float a, b; asm("mov.b64 {%0,%1}, %2;" : "=f"(a), "=f"(b) : "l"(v)); return a + b;
}
__device__ __forceinline__ ull ffma2(ull a, ull b, ull c) {
    ull d; asm("fma.rn.f32x2 %0, %1, %2, %3;" : "=l"(d) : "l"(a), "l"(b), "l"(c)); return d;
}
__device__ __forceinline__ ull fadd2(ull a, ull b) {
    ull d; asm("add.rn.f32x2 %0, %1, %2;" : "=l"(d) : "l"(a), "l"(b)); return d;
}
__device__ __forceinline__ float frcp(float x) {
    float r; asm("rcp.approx.f32 %0, %1;" : "=f"(r) : "f"(x)); return r;
}
__device__ __forceinline__ void cp16(float* s, const void* g) {
    unsigned a = (unsigned)__cvta_generic_to_shared(s);
    asm volatile("cp.async.cg.shared.global [%0], [%1], 16;" :: "r"(a), "l"(g));
}
__device__ __forceinline__ void cpcommit() { asm volatile("cp.async.commit_group;"); }
template<int N> __device__ __forceinline__ void cpwait() {
    asm volatile("cp.async.wait_group %0;" :: "n"(N));
}

__device__ __forceinline__ float sp(float x) {
    return fmaxf(x, 0.f) + log1pf(expf(-fabsf(x)));
}
__device__ __forceinline__ float phik(float z, float k) {
    float kz = k * z;
    if (fabsf(kz) < 1e-4f) return 1.f + 0.5f * kz;
    return expm1f(kz) / kz;
}

__device__ __forceinline__ ull dot64(const float* __restrict__ row, const ull* xr2) {
    ull a0 = 0, a1 = 0, a2 = 0, a3 = 0;
#pragma unroll
    for (int k = 0; k < 8; k++) {
        ulonglong2 w0 = *(const ulonglong2*)(row + 8 * k);
        ulonglong2 w1 = *(const ulonglong2*)(row + 8 * k + 4);
        a0 = ffma2(w0.x, xr2[4 * k + 0], a0);
        a1 = ffma2(w0.y, xr2[4 * k + 1], a1);
        a2 = ffma2(w1.x, xr2[4 * k + 2], a2);
        a3 = ffma2(w1.y, xr2[4 * k + 3], a3);
    }
    return fadd2(fadd2(a0, a2), fadd2(a1, a3));
}

// producer dynamic smem layout (float offsets)
#define SM_SX    0
#define SM_SPART 4224
#define SM_SSML  12416
#define SM_W0    14080
#define SM_W1    30464
#define SM_TOT   46848
#define SM_BYTES (SM_TOT * 4)

__device__ __forceinline__ void stageW512(const float* src, float* dst, int tid) {
    const float4* s4 = (const float4*)src;
#pragma unroll
    for (int i = 0; i < 8; i++) {
        int idx = tid + i * 512;
        cp16(dst + idx * 4, s4 + idx);
    }
}

// ---------------------------------------------------------------------------
// Fused kernel: blocks 0..31 = scanners (1 warp), blocks 32.. = producers.
// ---------------------------------------------------------------------------
__global__ __launch_bounds__(512, 1) void fused_kernel(
    const float* __restrict__ x, const float* __restrict__ y,
    const float* __restrict__ a_raw,
    const float* __restrict__ Wg, const float* __restrict__ bg,
    const float* __restrict__ WB, const float* __restrict__ bB,
    const float* __restrict__ WC, const float* __restrict__ bC,
    const float* __restrict__ Ws, const float* __restrict__ bs,
    const float* __restrict__ WR, const float* __restrict__ bR,
    const float* __restrict__ p0, float* __restrict__ out)
{
    // ---- scanner static smem ----
    __shared__ __align__(16) float rec[RECSZ];
    __shared__ __align__(16) float sP[320], sCP[160], sCPT[192], sKT[192];
    __shared__ __align__(16) float sS[72], se[8], hp[16], yps[8], Sd[8];

    if (blockIdx.x >= BB) {
        // ================= PRODUCER =================
        extern __shared__ float dsm[];
        float* sx    = dsm + SM_SX;
        float* spart = dsm + SM_SPART;
        float* ssml  = dsm + SM_SSML;
        float* sW0   = dsm + SM_W0;
        float* sW1   = dsm + SM_W1;

        const int tid = threadIdx.x;
        const int warp = tid >> 5, l = tid & 31;
        const int wf = warp & 7, half = warp >> 3;
        const int co = half * 64;
        const int p = blockIdx.x - BB;
        const int batch = p & 31, tchunk = p >> 5;         // time-major order
        const size_t base = (size_t)batch * TT + (size_t)tchunk * NTOK;

        stageW512(WB, sW0, tid);
        cpcommit();

        for (int k = tid; k < NTOK * DF; k += 512) {
            int tok = k >> 7, g = k & 127;
            sx[tok * 132 + g] = x[(base + tok) * DF + g];
        }
        __syncthreads();

        ull xr2[32];
#pragma unroll
        for (int k = 0; k < 16; k++) {
            ulonglong2 v = *(const ulonglong2*)(sx + l * 132 + co + 4 * k);
            xr2[2 * k] = v.x; xr2[2 * k + 1] = v.y;
        }

#pragma unroll
        for (int rr = 0; rr < 4; rr++) {
            int r = wf + 8 * rr;
            if (r < 25) {
                const float* Wrow; float bias;
                if (r == 0)      { Wrow = Wg;                 bias = bg[0]; }
                else if (r < 17) { Wrow = Ws + (r - 1) * DF;  bias = bs[r - 1]; }
                else             { Wrow = WR + (r - 17) * DF; bias = bR[r - 17]; }
                float v = sum2(dot64(Wrow + co, xr2));
                if (half == 0) v += bias;
                ssml[r * 66 + half * 33 + l] = v;
            }
        }

        for (int n = 0; n < NN; n++) {
            float* cur = (n & 1) ? sW1 : sW0;
            float* nxt = (n & 1) ? sW0 : sW1;
            __syncthreads();
            if (n < 15) { stageW512(WB + (size_t)(n + 1) * 16384, nxt, tid); cpcommit(); cpwait<1>(); }
            else        { cpwait<0>(); }
            __syncthreads();

            ull accn2 = 0;
            float bacc = 0.f;
#pragma unroll 4
            for (int fi = 0; fi < 16; fi++) {
                int f = wf + 8 * fi;
                ull rp = dot64(cur + f * 128 + co, xr2);
                float xf = sx[l * 132 + f];
                accn2 = ffma2(pk2(xf, xf), rp, accn2);
                if (half == 0) bacc += xf * bB[n * 128 + f];
            }
            spart[warp * 512 + n * 32 + l] = sum2(accn2) + bacc;
        }
        __syncthreads();

        stageW512(WC, sW0, tid);
        cpcommit();

        {
            int tok = tid & 31, n = tid >> 5;
            float hsum = 0.f;
#pragma unroll
            for (int w2 = 0; w2 < 16; w2++) hsum += spart[w2 * 512 + n * 32 + tok];
            float gate = ssml[tok] + ssml[33 + tok];
            float Delta = sp(gate) + 1e-6f;
            Delta = fminf(fmaxf(Delta, 1e-3f), 1.0f);
            float a = -(sp(a_raw[n]) + 1e-6f);
            float z = fminf(fmaxf(Delta * a, -20.f), 20.f);
            float ez  = expf(z);
            float gam = phik(z, 1.f);
            float rho = phik(z, 2.f);
            float sg = sp(ssml[(1 + n) * 66 + tok] + ssml[(1 + n) * 66 + 33 + tok]) + 1e-6f + 1e-3f;
            size_t rb = (base + tok) * RECSZ;
            g_rec[rb + n]      = ez;
            g_rec[rb + 16 + n] = gam * Delta * hsum;
            g_rec[rb + 32 + n] = sg * sg * rho * Delta;
            if (n < DY) {
                g_rec[rb + 176 + n] = sp(ssml[(17 + n) * 66 + tok] + ssml[(17 + n) * 66 + 33 + tok])
                                      + 1e-6f + 1e-4f;
                g_rec[rb + 184 + n] = y[(base + tok) * DY + n];
            }
        }
        cpwait<0>();
        __syncthreads();

#pragma unroll 4
        for (int jj = 0; jj < 16; jj++) {
            int j = wf * 16 + jj;
            spart[j * 64 + half * 32 + l] = sum2(dot64(sW0 + j * 128 + co, xr2));
        }
        __syncthreads();

        for (int idx = tid; idx < 1024; idx += 512) {
            int tok = idx & 31, j4 = (idx >> 5) * 4;
            float4 v;
            v.x = spart[(j4 + 0) * 64 + tok] + spart[(j4 + 0) * 64 + 32 + tok] + bC[j4 + 0];
            v.y = spart[(j4 + 1) * 64 + tok] + spart[(j4 + 1) * 64 + 32 + tok] + bC[j4 + 1];
            v.z = spart[(j4 + 2) * 64 + tok] + spart[(j4 + 2) * 64 + 32 + tok] + bC[j4 + 2];
            v.w = spart[(j4 + 3) * 64 + tok] + spart[(j4 + 3) * 64 + 32 + tok] + bC[j4 + 3];
            *(float4*)(&g_rec[(base + tok) * RECSZ + 48 + j4]) = v;
        }

        // publish chunk
        __threadfence();
        __syncthreads();
        if (tid == 0) atomicExch(&g_flag[batch * NCHUNK + tchunk], 1);
        return;
    }

    // ================= SCANNER (1 warp per batch) =================
    const int b = blockIdx.x, l = threadIdx.x;
    if (l >= 32) return;
    const unsigned FULL = 0xffffffffu;

    const int i2 = l >> 1, jb = (l & 1) * 8;
    const int d4 = l >> 2, j04 = (l & 3) * 4;

#pragma unroll
    for (int u = 0; u < 8; u++)
        sP[i2 * 20 + jb + u] = (i2 == jb + u) ? fabsf(p0[i2]) : 0.f;
    float hh_reg = 0.f, hp_reg = 0.f;            // lanes < 16
    float ll_s = 0.f, ll_c = 0.f;                // lane 24

    // wait chunk 0, prefetch record 0
    {
        volatile int* f = &g_flag[b * NCHUNK];
        while (*f == 0) __nanosleep(64);
    }
    __threadfence();
    const float* RB = g_rec + (size_t)b * TT * RECSZ;
    float4 pfa = *(const float4*)(RB + l * 8);
    float4 pfb = *(const float4*)(RB + l * 8 + 4);

    float* om = out;
    float* ov = out + (size_t)BB * TT * DY;

    for (int t = 0; t < TT; t++) {
        __syncwarp(FULL);                        // everyone done with prev rec
        *(float4*)(rec + l * 8) = pfa;
        *(float4*)(rec + l * 8 + 4) = pfb;
        __syncwarp(FULL);
        {
            int tn = (t + 1 < TT) ? t + 1 : t;
            if (tn > t && (tn & 31) == 0) {
                volatile int* f = &g_flag[b * NCHUNK + (tn >> 5)];
                while (*f == 0) __nanosleep(64);
                __threadfence();
            }
            const float* nx = RB + (size_t)tn * RECSZ;
            pfa = *(const float4*)(nx + l * 8);
            pfb = *(const float4*)(nx + l * 8 + 4);
        }

        // ---- hp (lanes<16, register + smem) ----
        if (l < 16) {
            hp_reg = rec[l] * hh_reg + rec[16 + l];
            hp[l] = hp_reg;
        }

        // ---- CP directly from P:  CP[d][j] = ez_j*(sum_n C[d][n] ez_n P[n][j]) + C[d][j] q_j
        {
            float4 ez0 = *(const float4*)&rec[0];
            float4 ez1 = *(const float4*)&rec[4];
            float4 ez2 = *(const float4*)&rec[8];
            float4 ez3 = *(const float4*)&rec[12];
            float ezl[16] = {ez0.x,ez0.y,ez0.z,ez0.w, ez1.x,ez1.y,ez1.z,ez1.w,
                             ez2.x,ez2.y,ez2.z,ez2.w, ez3.x,ez3.y,ez3.z,ez3.w};
            const float* Crow = rec + 48 + d4 * 16;
            float4 ca = *(const float4*)(Crow);
            float4 cb = *(const float4*)(Crow + 4);
            float4 cc = *(const float4*)(Crow + 8);
            float4 cd = *(const float4*)(Crow + 12);
            float C[16] = {ca.x,ca.y,ca.z,ca.w, cb.x,cb.y,cb.z,cb.w,
                           cc.x,cc.y,cc.z,cc.w, cd.x,cd.y,cd.z,cd.w};
            float4 qv  = *(const float4*)&rec[32 + j04];
            float4 ezj = *(const float4*)&rec[j04];
            float aA0=0.f,aA1=0.f,aA2=0.f,aA3=0.f;
            float aB0=0.f,aB1=0.f,aB2=0.f,aB3=0.f;
#pragma unroll
            for (int n = 0; n < 16; n += 2) {
                float chA = C[n] * ezl[n];
                float chB = C[n + 1] * ezl[n + 1];
                float4 pA = *(const float4*)&sP[n * 20 + j04];
                float4 pB = *(const float4*)&sP[(n + 1) * 20 + j04];
                aA0 += chA * pA.x; aA1 += chA * pA.y; aA2 += chA * pA.z; aA3 += chA * pA.w;
                aB0 += chB * pB.x; aB1 += chB * pB.y; aB2 += chB * pB.z; aB3 += chB * pB.w;
            }
            float4 cp;
            cp.x = ezj.x * (aA0 + aB0) + C[j04 + 0] * qv.x;
            cp.y = ezj.y * (aA1 + aB1) + C[j04 + 1] * qv.y;
            cp.z = ezj.z * (aA2 + aB2) + C[j04 + 2] * qv.z;
            cp.w = ezj.w * (aA3 + aB3) + C[j04 + 3] * qv.w;
            *(float4*)&sCP[d4 * 20 + j04] = cp;
            sCPT[(j04 + 0) * 12 + d4] = cp.x;
            sCPT[(j04 + 1) * 12 + d4] = cp.y;
            sCPT[(j04 + 2) * 12 + d4] = cp.z;
            sCPT[(j04 + 3) * 12 + d4] = cp.w;
        }
        __syncwarp(FULL);

        // ---- S (2 per lane) + y_pred/e (lanes 24..31) ----
        {
            int d = d4, q0 = (l & 3) * 2;
            ulonglong2 g0 = *(const ulonglong2*)&sCP[d * 20];
            ulonglong2 g1 = *(const ulonglong2*)&sCP[d * 20 + 4];
            ulonglong2 g2 = *(const ulonglong2*)&sCP[d * 20 + 8];
            ulonglong2 g3 = *(const ulonglong2*)&sCP[d * 20 + 12];
#pragma unroll
            for (int qq = 0; qq < 2; qq++) {
                int q = q0 + qq;
                ulonglong2 c0 = *(const ulonglong2*)&rec[48 + q * 16];
                ulonglong2 c1 = *(const ulonglong2*)&rec[48 + q * 16 + 4];
                ulonglong2 c2 = *(const ulonglong2*)&rec[48 + q * 16 + 8];
                ulonglong2 c3 = *(const ulonglong2*)&rec[48 + q * 16 + 12];
                ull x0 = ffma2(g0.x, c0.x, ffma2(g0.y, c0.y, 0));
                ull x1 = ffma2(g1.x, c1.x, ffma2(g1.y, c1.y, 0));
                ull x2 = ffma2(g2.x, c2.x, ffma2(g2.y, c2.y, 0));
                ull x3 = ffma2(g3.x, c3.x, ffma2(g3.y, c3.y, 0));
                float s = sum2(fadd2(fadd2(x0, x1), fadd2(x2, x3)));
                if (d == q) { s += rec[176 + d]; Sd[d] = s; }
                sS[d * 9 + q] = s;
            }
            if (l >= 24) {
                int dd = l - 24;
                float yp = 0.f;
#pragma unroll
                for (int n = 0; n < 16; n++) yp += rec[48 + dd * 16 + n] * hp[n];
                yps[dd] = yp;
                se[dd] = rec[184 + dd] - yp;
            }
        }
        __syncwarp(FULL);

        // ---- Gauss-Jordan on [S | CP | e]: lane = column ----
        float r[8];
        if (l < 8) {
#pragma unroll
            for (int d = 0; d < 8; d++) r[d] = sS[d * 9 + l];
        } else if (l < 24) {
            int m = l - 8;
#pragma unroll
            for (int d = 0; d < 8; d++) r[d] = sCP[d * 20 + m];
        } else if (l == 24) {
#pragma unroll
            for (int d = 0; d < 8; d++) r[d] = se[d];
        } else {
#pragma unroll
            for (int d = 0; d < 8; d++) r[d] = 0.f;
        }
        float pprod = 1.f;
#pragma unroll
        for (int k = 0; k < 8; k++) {
            float piv = __shfl_sync(FULL, r[k], k);
            pprod *= piv;
            float pinv = frcp(piv);
            r[k] *= pinv;
#pragma unroll
            for (int i = 0; i < 8; i++) if (i != k) {
                float m = __shfl_sync(FULL, r[i], k);
                r[i] -= m * r[k];
            }
        }
        if (l >= 8 && l < 24) {
            int m = l - 8;
#pragma unroll
            for (int d = 0; d < 8; d++) sKT[m * 12 + d] = r[d];
        }
        __syncwarp(FULL);

        // ---- h_new (reg), ll (lane 24), P_new (all lanes), outputs ----
        if (l < 16) {
            ulonglong2 k0 = *(const ulonglong2*)&sKT[l * 12];
            ulonglong2 k1 = *(const ulonglong2*)&sKT[l * 12 + 4];
            ulonglong2 e0 = *(const ulonglong2*)&se[0];
            ulonglong2 e1 = *(const ulonglong2*)&se[4];
            ull acc = ffma2(k0.x, e0.x, ffma2(k0.y, e0.y,
                      ffma2(k1.x, e1.x, ffma2(k1.y, e1.y, 0))));
            hh_reg = hp_reg + sum2(acc);
        }
        if (l == 24) {
            float quad = 0.f;
#pragma unroll
            for (int d = 0; d < 8; d++) quad += se[d] * r[d];
            float ll = -0.5f * (logf(pprod) + quad + (float)DY * LOG2PI);
            float yk = ll - ll_c, tk = ll_s + yk;
            ll_c = (tk - ll_s) - yk; ll_s = tk;
        }
        {
            float ezi = rec[i2];
            float qi  = rec[32 + i2];
            float4 ej0 = *(const float4*)&rec[jb];
            float4 ej1 = *(const float4*)&rec[jb + 4];
            float ej[8] = {ej0.x,ej0.y,ej0.z,ej0.w, ej1.x,ej1.y,ej1.z,ej1.w};
            float4 pa = *(const float4*)&sP[i2 * 20 + jb];
            float4 pb = *(const float4*)&sP[i2 * 20 + jb + 4];
            float pv[8] = {pa.x,pa.y,pa.z,pa.w, pb.x,pb.y,pb.z,pb.w};
            ulonglong2 K0 = *(const ulonglong2*)&sKT[i2 * 12];
            ulonglong2 K1 = *(const ulonglong2*)&sKT[i2 * 12 + 4];
            float o[8];
#pragma unroll
            for (int u = 0; u < 8; u++) {
                int j = jb + u;
                ulonglong2 c0 = *(const ulonglong2*)&sCPT[j * 12];
                ulonglong2 c1 = *(const ulonglong2*)&sCPT[j * 12 + 4];
                ull acc = ffma2(K0.x, c0.x, ffma2(K0.y, c0.y,
                          ffma2(K1.x, c1.x, ffma2(K1.y, c1.y, 0))));
                o[u] = ezi * ej[u] * pv[u] - sum2(acc) + ((i2 == j) ? qi : 0.f);
            }
            *(float4*)&sP[i2 * 20 + jb]     = make_float4(o[0], o[1], o[2], o[3]);
            *(float4*)&sP[i2 * 20 + jb + 4] = make_float4(o[4], o[5], o[6], o[7]);
        }
        if (l < DY) {
            size_t o = ((size_t)b * TT + t) * DY + l;
            om[o] = yps[l];
            ov[o] = Sd[l];
        }
    }
    if (l == 24) g_llsum[b] = ll_s;
}

__global__ void phase3_kernel(float* __restrict__ out) {
    float v = g_llsum[threadIdx.x];
#pragma unroll
    for (int o = 16; o > 0; o >>= 1) v += __shfl_down_sync(0xffffffffu, v, o);
    if (threadIdx.x == 0) {
        size_t off = (size_t)2 * BB * TT * DY;
        out[off]     = -v / (float)BB;
        out[off + 1] =  v / (float)(BB * TT);
    }
}

extern "C" void kernel_launch(void* const* d_in, const int* in_sizes, int n_in,
                              void* d_out, int out_size) {
    const float* x_feat = (const float*)d_in[0];
    const float* y      = (const float*)d_in[1];
    const float* a_raw  = (const float*)d_in[2];
    const float* W_gate = (const float*)d_in[3];
    const float* b_gate = (const float*)d_in[4];
    const float* W_B    = (const float*)d_in[5];
    const float* b_B    = (const float*)d_in[6];
    const float* W_C    = (const float*)d_in[7];
    const float* b_C    = (const float*)d_in[8];
    const float* W_sig  = (const float*)d_in[9];
    const float* b_sig  = (const float*)d_in[10];
    const float* W_R    = (const float*)d_in[11];
    const float* b_R    = (const float*)d_in[12];
    const float* p0     = (const float*)d_in[13];
    float* out = (float*)d_out;

    void* flag_ptr = nullptr;
    cudaGetSymbolAddress(&flag_ptr, g_flag);
    cudaMemsetAsync(flag_ptr, 0, BB * NCHUNK * sizeof(int), 0);

    cudaFuncSetAttribute(fused_kernel,
                         cudaFuncAttributeMaxDynamicSharedMemorySize, SM_BYTES);
    fused_kernel<<<BB + (BB * TT) / NTOK, 512, SM_BYTES>>>(
        x_feat, y, a_raw, W_gate, b_gate, W_B, b_B, W_C, b_C,
        W_sig, b_sig, W_R, b_R, p0, out);
    phase3_kernel<<<1, 32>>>(out);
}

// round 8
// speedup vs baseline: 3.3040x; 1.0507x over previous
#include <cuda_runtime.h>
#include <math.h>

#define BB 32
#define TT 2048
#define DF 128
#define NN 16
#define DY 8
#define RECSZ 256
#define NTOK 32
#define NCHUNK 64                 // TT / NTOK
#define LOG2PI 1.8378770664093455f

__device__ float g_rec[(size_t)BB * TT * RECSZ];   // zero-init; pad [192,256) never written
__device__ float g_llsum[BB];
__device__ int   g_flag[BB * NCHUNK];              // memset to 0 each launch

typedef unsigned long long ull;

__device__ __forceinline__ ull pk2(float a, float b) {
    ull r; asm("mov.b64 %0, {%1,%2};" : "=l"(r) : "f"(a), "f"(b)); return r;
}
__device__ __forceinline__ float sum2(ull v) {
    float a, b; asm("mov.b64 {%0,%1}, %2;" : "=f"(a), "=f"(b) : "l"(v)); return a + b;
}
__device__ __forceinline__ ull ffma2(ull a, ull b, ull c) {
    ull d; asm("fma.rn.f32x2 %0, %1, %2, %3;" : "=l"(d) : "l"(a), "l"(b), "l"(c)); return d;
}
__device__ __forceinline__ ull fadd2(ull a, ull b) {
    ull d; asm("add.rn.f32x2 %0, %1, %2;" : "=l"(d) : "l"(a), "l"(b)); return d;
}
__device__ __forceinline__ float frcp(float x) {
    float r; asm("rcp.approx.f32 %0, %1;" : "=f"(r) : "f"(x)); return r;
}
__device__ __forceinline__ void cp16(float* s, const void* g) {
    unsigned a = (unsigned)__cvta_generic_to_shared(s);
    asm volatile("cp.async.cg.shared.global [%0], [%1], 16;" :: "r"(a), "l"(g));
}
__device__ __forceinline__ void cpcommit() { asm volatile("cp.async.commit_group;"); }
template<int N> __device__ __forceinline__ void cpwait() {
    asm volatile("cp.async.wait_group %0;" :: "n"(N));
}

__device__ __forceinline__ float sp(float x) {
    return fmaxf(x, 0.f) + log1pf(expf(-fabsf(x)));
}
__device__ __forceinline__ float phik(float z, float k) {
    float kz = k * z;
    if (fabsf(kz) < 1e-4f) return 1.f + 0.5f * kz;
    return expm1f(kz) / kz;
}

__device__ __forceinline__ ull dot64(const float* __restrict__ row, const ull* xr2) {
    ull a0 = 0, a1 = 0, a2 = 0, a3 = 0;
#pragma unroll
    for (int k = 0; k < 8; k++) {
        ulonglong2 w0 = *(const ulonglong2*)(row + 8 * k);
        ulonglong2 w1 = *(const ulonglong2*)(row + 8 * k + 4);
        a0 = ffma2(w0.x, xr2[4 * k + 0], a0);
        a1 = ffma2(w0.y, xr2[4 * k + 1], a1);
        a2 = ffma2(w1.x, xr2[4 * k + 2], a2);
        a3 = ffma2(w1.y, xr2[4 * k + 3], a3);
    }
    return fadd2(fadd2(a0, a2), fadd2(a1, a3));
}

// producer dynamic smem layout (float offsets)
#define SM_SX    0
#define SM_SPART 4224
#define SM_SSML  12416
#define SM_W0    14080
#define SM_W1    30464
#define SM_TOT   46848
#define SM_BYTES (SM_TOT * 4)

__device__ __forceinline__ void stageW512(const float* src, float* dst, int tid) {
    const float4* s4 = (const float4*)src;
#pragma unroll
    for (int i = 0; i < 8; i++) {
        int idx = tid + i * 512;
        cp16(dst + idx * 4, s4 + idx);
    }
}

// ---------------------------------------------------------------------------
// Fused kernel: blocks 0..31 = scanners (1 warp), blocks 32.. = producers.
// ---------------------------------------------------------------------------
__global__ __launch_bounds__(512, 1) void fused_kernel(
    const float* __restrict__ x, const float* __restrict__ y,
    const float* __restrict__ a_raw,
    const float* __restrict__ Wg, const float* __restrict__ bg,
    const float* __restrict__ WB, const float* __restrict__ bB,
    const float* __restrict__ WC, const float* __restrict__ bC,
    const float* __restrict__ Ws, const float* __restrict__ bs,
    const float* __restrict__ WR, const float* __restrict__ bR,
    const float* __restrict__ p0, float* __restrict__ out)
{
    // ---- scanner static smem ----
    __shared__ __align__(16) float rec2[2][RECSZ];
    __shared__ __align__(16) float sP[320], sCP[160], sCPT[192], sKT[192];
    __shared__ __align__(16) float sS[72], se[8], hp[16], yps[8], Sd[8];

    if (blockIdx.x >= BB) {
        // ================= PRODUCER =================
        extern __shared__ float dsm[];
        float* sx    = dsm + SM_SX;
        float* spart = dsm + SM_SPART;
        float* ssml  = dsm + SM_SSML;
        float* sW0   = dsm + SM_W0;
        float* sW1   = dsm + SM_W1;

        const int tid = threadIdx.x;
        const int warp = tid >> 5, l = tid & 31;
        const int wf = warp & 7, half = warp >> 3;
        const int co = half * 64;
        const int p = blockIdx.x - BB;
        const int batch = p & 31, tchunk = p >> 5;         // time-major order
        const size_t base = (size_t)batch * TT + (size_t)tchunk * NTOK;

        stageW512(WB, sW0, tid);
        cpcommit();

        for (int k = tid; k < NTOK * DF; k += 512) {
            int tok = k >> 7, g = k & 127;
            sx[tok * 132 + g] = x[(base + tok) * DF + g];
        }
        __syncthreads();

        ull xr2[32];
#pragma unroll
        for (int k = 0; k < 16; k++) {
            ulonglong2 v = *(const ulonglong2*)(sx + l * 132 + co + 4 * k);
            xr2[2 * k] = v.x; xr2[2 * k + 1] = v.y;
        }

#pragma unroll
        for (int rr = 0; rr < 4; rr++) {
            int r = wf + 8 * rr;
            if (r < 25) {
                const float* Wrow; float bias;
                if (r == 0)      { Wrow = Wg;                 bias = bg[0]; }
                else if (r < 17) { Wrow = Ws + (r - 1) * DF;  bias = bs[r - 1]; }
                else             { Wrow = WR + (r - 17) * DF; bias = bR[r - 17]; }
                float v = sum2(dot64(Wrow + co, xr2));
                if (half == 0) v += bias;
                ssml[r * 66 + half * 33 + l] = v;
            }
        }

        for (int n = 0; n < NN; n++) {
            float* cur = (n & 1) ? sW1 : sW0;
            float* nxt = (n & 1) ? sW0 : sW1;
            __syncthreads();
            if (n < 15) { stageW512(WB + (size_t)(n + 1) * 16384, nxt, tid); cpcommit(); cpwait<1>(); }
            else        { cpwait<0>(); }
            __syncthreads();

            ull accn2 = 0;
            float bacc = 0.f;
#pragma unroll 4
            for (int fi = 0; fi < 16; fi++) {
                int f = wf + 8 * fi;
                ull rp = dot64(cur + f * 128 + co, xr2);
                float xf = sx[l * 132 + f];
                accn2 = ffma2(pk2(xf, xf), rp, accn2);
                if (half == 0) bacc += xf * bB[n * 128 + f];
            }
            spart[warp * 512 + n * 32 + l] = sum2(accn2) + bacc;
        }
        __syncthreads();

        stageW512(WC, sW0, tid);
        cpcommit();

        {
            int tok = tid & 31, n = tid >> 5;
            float hsum = 0.f;
#pragma unroll
            for (int w2 = 0; w2 < 16; w2++) hsum += spart[w2 * 512 + n * 32 + tok];
            float gate = ssml[tok] + ssml[33 + tok];
            float Delta = sp(gate) + 1e-6f;
            Delta = fminf(fmaxf(Delta, 1e-3f), 1.0f);
            float a = -(sp(a_raw[n]) + 1e-6f);
            float z = fminf(fmaxf(Delta * a, -20.f), 20.f);
            float ez  = expf(z);
            float gam = phik(z, 1.f);
            float rho = phik(z, 2.f);
            float sg = sp(ssml[(1 + n) * 66 + tok] + ssml[(1 + n) * 66 + 33 + tok]) + 1e-6f + 1e-3f;
            size_t rb = (base + tok) * RECSZ;
            g_rec[rb + n]      = ez;
            g_rec[rb + 16 + n] = gam * Delta * hsum;
            g_rec[rb + 32 + n] = sg * sg * rho * Delta;
            if (n < DY) {
                g_rec[rb + 176 + n] = sp(ssml[(17 + n) * 66 + tok] + ssml[(17 + n) * 66 + 33 + tok])
                                      + 1e-6f + 1e-4f;
                g_rec[rb + 184 + n] = y[(base + tok) * DY + n];
            }
        }
        cpwait<0>();
        __syncthreads();

#pragma unroll 4
        for (int jj = 0; jj < 16; jj++) {
            int j = wf * 16 + jj;
            spart[j * 64 + half * 32 + l] = sum2(dot64(sW0 + j * 128 + co, xr2));
        }
        __syncthreads();

        for (int idx = tid; idx < 1024; idx += 512) {
            int tok = idx & 31, j4 = (idx >> 5) * 4;
            float4 v;
            v.x = spart[(j4 + 0) * 64 + tok] + spart[(j4 + 0) * 64 + 32 + tok] + bC[j4 + 0];
            v.y = spart[(j4 + 1) * 64 + tok] + spart[(j4 + 1) * 64 + 32 + tok] + bC[j4 + 1];
            v.z = spart[(j4 + 2) * 64 + tok] + spart[(j4 + 2) * 64 + 32 + tok] + bC[j4 + 2];
            v.w = spart[(j4 + 3) * 64 + tok] + spart[(j4 + 3) * 64 + 32 + tok] + bC[j4 + 3];
            *(float4*)(&g_rec[(base + tok) * RECSZ + 48 + j4]) = v;
        }

        // publish chunk
        __threadfence();
        __syncthreads();
        if (tid == 0) atomicExch(&g_flag[batch * NCHUNK + tchunk], 1);
        return;
    }

    // ================= SCANNER (1 warp per batch) =================
    const int b = blockIdx.x, l = threadIdx.x;
    if (l >= 32) return;
    const unsigned FULL = 0xffffffffu;

    const int i2 = l >> 1, jb = (l & 1) * 8;
    const int d4 = l >> 2, j04 = (l & 3) * 4;

#pragma unroll
    for (int u = 0; u < 8; u++)
        sP[i2 * 20 + jb + u] = (i2 == jb + u) ? fabsf(p0[i2]) : 0.f;
    float hh_reg = 0.f, hp_reg = 0.f;            // lanes < 16
    float ll_s = 0.f, ll_c = 0.f;                // lane 24

    // wait chunk 0, stage record 0 into buffer 0
    {
        volatile int* f = &g_flag[b * NCHUNK];
        while (*f == 0) __nanosleep(64);
    }
    __threadfence();
    const float* RB = g_rec + (size_t)b * TT * RECSZ;
    {
        float4 a0 = *(const float4*)(RB + l * 8);
        float4 a1 = *(const float4*)(RB + l * 8 + 4);
        *(float4*)(&rec2[0][l * 8])     = a0;
        *(float4*)(&rec2[0][l * 8 + 4]) = a1;
    }

    float* om = out;
    float* ov = out + (size_t)BB * TT * DY;

    for (int t = 0; t < TT; t++) {
        __syncwarp(FULL);           // rec buffer + sP from prev iter visible
        const float* rec = rec2[t & 1];
        float* rnx = rec2[(t + 1) & 1];

        // prefetch next record (LDG issued early, STS at iter bottom)
        float4 pfa, pfb;
        {
            int tn = (t + 1 < TT) ? t + 1 : t;
            if (tn > t && (tn & 31) == 0) {
                volatile int* f = &g_flag[b * NCHUNK + (tn >> 5)];
                while (*f == 0) __nanosleep(64);
                __threadfence();
            }
            const float* nx = RB + (size_t)tn * RECSZ;
            pfa = *(const float4*)(nx + l * 8);
            pfb = *(const float4*)(nx + l * 8 + 4);
        }

        // ---- hp (lanes<16) ----
        if (l < 16) {
            hp_reg = rec[l] * hh_reg + rec[16 + l];
            hp[l] = hp_reg;
        }

        // ---- CP directly from P:  CP[d][j] = ez_j*(sum_n C[d][n] ez_n P[n][j]) + C[d][j] q_j
        {
            float4 ez0 = *(const float4*)&rec[0];
            float4 ez1 = *(const float4*)&rec[4];
            float4 ez2 = *(const float4*)&rec[8];
            float4 ez3 = *(const float4*)&rec[12];
            float ezl[16] = {ez0.x,ez0.y,ez0.z,ez0.w, ez1.x,ez1.y,ez1.z,ez1.w,
                             ez2.x,ez2.y,ez2.z,ez2.w, ez3.x,ez3.y,ez3.z,ez3.w};
            const float* Crow = rec + 48 + d4 * 16;
            float4 ca = *(const float4*)(Crow);
            float4 cb = *(const float4*)(Crow + 4);
            float4 cc = *(const float4*)(Crow + 8);
            float4 cd = *(const float4*)(Crow + 12);
            float C[16] = {ca.x,ca.y,ca.z,ca.w, cb.x,cb.y,cb.z,cb.w,
                           cc.x,cc.y,cc.z,cc.w, cd.x,cd.y,cd.z,cd.w};
            float4 qv  = *(const float4*)&rec[32 + j04];
            float4 ezj = *(const float4*)&rec[j04];
            float aA0=0.f,aA1=0.f,aA2=0.f,aA3=0.f;
            float aB0=0.f,aB1=0.f,aB2=0.f,aB3=0.f;
#pragma unroll
            for (int n = 0; n < 16; n += 2) {
                float chA = C[n] * ezl[n];
                float chB = C[n + 1] * ezl[n + 1];
                float4 pA = *(const float4*)&sP[n * 20 + j04];
                float4 pB = *(const float4*)&sP[(n + 1) * 20 + j04];
                aA0 += chA * pA.x; aA1 += chA * pA.y; aA2 += chA * pA.z; aA3 += chA * pA.w;
                aB0 += chB * pB.x; aB1 += chB * pB.y; aB2 += chB * pB.z; aB3 += chB * pB.w;
            }
            float4 cp;
            cp.x = ezj.x * (aA0 + aB0) + C[j04 + 0] * qv.x;
            cp.y = ezj.y * (aA1 + aB1) + C[j04 + 1] * qv.y;
            cp.z = ezj.z * (aA2 + aB2) + C[j04 + 2] * qv.z;
            cp.w = ezj.w * (aA3 + aB3) + C[j04 + 3] * qv.w;
            *(float4*)&sCP[d4 * 20 + j04] = cp;
            sCPT[(j04 + 0) * 12 + d4] = cp.x;
            sCPT[(j04 + 1) * 12 + d4] = cp.y;
            sCPT[(j04 + 2) * 12 + d4] = cp.z;
            sCPT[(j04 + 3) * 12 + d4] = cp.w;
        }
        __syncwarp(FULL);

        // ---- S (2 per lane) + y_pred/e (lanes 24..31) ----
        {
            int d = d4, q0 = (l & 3) * 2;
            ulonglong2 g0 = *(const ulonglong2*)&sCP[d * 20];
            ulonglong2 g1 = *(const ulonglong2*)&sCP[d * 20 + 4];
            ulonglong2 g2 = *(const ulonglong2*)&sCP[d * 20 + 8];
            ulonglong2 g3 = *(const ulonglong2*)&sCP[d * 20 + 12];
#pragma unroll
            for (int qq = 0; qq < 2; qq++) {
                int q = q0 + qq;
                ulonglong2 c0 = *(const ulonglong2*)&rec[48 + q * 16];
                ulonglong2 c1 = *(const ulonglong2*)&rec[48 + q * 16 + 4];
                ulonglong2 c2 = *(const ulonglong2*)&rec[48 + q * 16 + 8];
                ulonglong2 c3 = *(const ulonglong2*)&rec[48 + q * 16 + 12];
                ull x0 = ffma2(g0.x, c0.x, ffma2(g0.y, c0.y, 0));
                ull x1 = ffma2(g1.x, c1.x, ffma2(g1.y, c1.y, 0));
                ull x2 = ffma2(g2.x, c2.x, ffma2(g2.y, c2.y, 0));
                ull x3 = ffma2(g3.x, c3.x, ffma2(g3.y, c3.y, 0));
                float s = sum2(fadd2(fadd2(x0, x1), fadd2(x2, x3)));
                if (d == q) { s += rec[176 + d]; Sd[d] = s; }
                sS[d * 9 + q] = s;
            }
            if (l >= 24) {
                int dd = l - 24;
                float yp = 0.f;
#pragma unroll
                for (int n = 0; n < 16; n++) yp += rec[48 + dd * 16 + n] * hp[n];
                yps[dd] = yp;
                se[dd] = rec[184 + dd] - yp;
            }
        }
        __syncwarp(FULL);

        // ---- 2x2 block Gauss-Jordan on [S | CP | e]: lane = column ----
        float r[8];
        if (l < 8) {
#pragma unroll
            for (int d = 0; d < 8; d++) r[d] = sS[d * 9 + l];
        } else if (l < 24) {
            int m = l - 8;
#pragma unroll
            for (int d = 0; d < 8; d++) r[d] = sCP[d * 20 + m];
        } else if (l == 24) {
#pragma unroll
            for (int d = 0; d < 8; d++) r[d] = se[d];
        } else {
#pragma unroll
            for (int d = 0; d < 8; d++) r[d] = 0.f;
        }
        float pprod = 1.f;
#pragma unroll
        for (int k = 0; k < 4; k++) {
            const int p0i = 2 * k, p1i = 2 * k + 1;
            float r0 = r[p0i], r1 = r[p1i];
            // pivot block entries from column-lanes p0i, p1i
            float pa = __shfl_sync(FULL, r0, p0i);   // A[p0][p0]
            float pc = __shfl_sync(FULL, r1, p0i);   // A[p1][p0]
            float pb = __shfl_sync(FULL, r0, p1i);   // A[p0][p1]
            float pd = __shfl_sync(FULL, r1, p1i);   // A[p1][p1]
            float det = pa * pd - pb * pc;
            pprod *= det;
            float rdet = frcp(det);
            float n0 = rdet * (pd * r0 - pb * r1);   // normalized pivot row p0
            float n1 = rdet * (pa * r1 - pc * r0);   // normalized pivot row p1
#pragma unroll
            for (int i = 0; i < 8; i++) {
                if (i == p0i || i == p1i) continue;
                float m0 = __shfl_sync(FULL, r[i], p0i);
                float m1 = __shfl_sync(FULL, r[i], p1i);
                r[i] -= m0 * n0 + m1 * n1;
            }
            r[p0i] = n0; r[p1i] = n1;
        }
        if (l >= 8 && l < 24) {
            int m = l - 8;
#pragma unroll
            for (int d = 0; d < 8; d++) sKT[m * 12 + d] = r[d];
        }
        __syncwarp(FULL);

        // ---- h_new (reg), ll (lane 24), P_new (all lanes), outputs ----
        if (l < 16) {
            ulonglong2 k0 = *(const ulonglong2*)&sKT[l * 12];
            ulonglong2 k1 = *(const ulonglong2*)&sKT[l * 12 + 4];
            ulonglong2 e0 = *(const ulonglong2*)&se[0];
            ulonglong2 e1 = *(const ulonglong2*)&se[4];
            ull acc = ffma2(k0.x, e0.x, ffma2(k0.y, e0.y,
                      ffma2(k1.x, e1.x, ffma2(k1.y, e1.y, 0))));
            hh_reg = hp_reg + sum2(acc);
        }
        if (l == 24) {
            float quad = 0.f;
#pragma unroll
            for (int d = 0; d < 8; d++) quad += se[d] * r[d];
            float ll = -0.5f * (logf(pprod) + quad + (float)DY * LOG2PI);
            float yk = ll - ll_c, tk = ll_s + yk;
            ll_c = (tk - ll_s) - yk; ll_s = tk;
        }
        {
            float ezi = rec[i2];
            float qi  = rec[32 + i2];
            float4 ej0 = *(const float4*)&rec[jb];
            float4 ej1 = *(const float4*)&rec[jb + 4];
            float ej[8] = {ej0.x,ej0.y,ej0.z,ej0.w, ej1.x,ej1.y,ej1.z,ej1.w};
            float4 pav = *(const float4*)&sP[i2 * 20 + jb];
            float4 pbv = *(const float4*)&sP[i2 * 20 + jb + 4];
            float pv[8] = {pav.x,pav.y,pav.z,pav.w, pbv.x,pbv.y,pbv.z,pbv.w};
            ulonglong2 K0 = *(const ulonglong2*)&sKT[i2 * 12];
            ulonglong2 K1 = *(const ulonglong2*)&sKT[i2 * 12 + 4];
            float o[8];
#pragma unroll
            for (int u = 0; u < 8; u++) {
                int j = jb + u;
                ulonglong2 c0 = *(const ulonglong2*)&sCPT[j * 12];
                ulonglong2 c1 = *(const ulonglong2*)&sCPT[j * 12 + 4];
                ull acc = ffma2(K0.x, c0.x, ffma2(K0.y, c0.y,
                          ffma2(K1.x, c1.x, ffma2(K1.y, c1.y, 0))));
                o[u] = ezi * ej[u] * pv[u] - sum2(acc) + ((i2 == j) ? qi : 0.f);
            }
            *(float4*)&sP[i2 * 20 + jb]     = make_float4(o[0], o[1], o[2], o[3]);
            *(float4*)&sP[i2 * 20 + jb + 4] = make_float4(o[4], o[5], o[6], o[7]);
        }
        if (l < DY) {
            size_t o = ((size_t)b * TT + t) * DY + l;
            om[o] = yps[l];
            ov[o] = Sd[l];
        }
        // stage next record into the other buffer (visible after loop-top sync)
        *(float4*)(&rnx[l * 8])     = pfa;
        *(float4*)(&rnx[l * 8 + 4]) = pfb;
    }
    if (l == 24) g_llsum[b] = ll_s;
}

__global__ void phase3_kernel(float* __restrict__ out) {
    float v = g_llsum[threadIdx.x];
#pragma unroll
    for (int o = 16; o > 0; o >>= 1) v += __shfl_down_sync(0xffffffffu, v, o);
    if (threadIdx.x == 0) {
        size_t off = (size_t)2 * BB * TT * DY;
        out[off]     = -v / (float)BB;
        out[off + 1] =  v / (float)(BB * TT);
    }
}

extern "C" void kernel_launch(void* const* d_in, const int* in_sizes, int n_in,
                              void* d_out, int out_size) {
    const float* x_feat = (const float*)d_in[0];
    const float* y      = (const float*)d_in[1];
    const float* a_raw  = (const float*)d_in[2];
    const float* W_gate = (const float*)d_in[3];
    const float* b_gate = (const float*)d_in[4];
    const float* W_B    = (const float*)d_in[5];
    const float* b_B    = (const float*)d_in[6];
    const float* W_C    = (const float*)d_in[7];
    const float* b_C    = (const float*)d_in[8];
    const float* W_sig  = (const float*)d_in[9];
    const float* b_sig  = (const float*)d_in[10];
    const float* W_R    = (const float*)d_in[11];
    const float* b_R    = (const float*)d_in[12];
    const float* p0     = (const float*)d_in[13];
    float* out = (float*)d_out;

    void* flag_ptr = nullptr;
    cudaGetSymbolAddress(&flag_ptr, g_flag);
    cudaMemsetAsync(flag_ptr, 0, BB * NCHUNK * sizeof(int), 0);

    cudaFuncSetAttribute(fused_kernel,
                         cudaFuncAttributeMaxDynamicSharedMemorySize, SM_BYTES);
    fused_kernel<<<BB + (BB * TT) / NTOK, 512, SM_BYTES>>>(
        x_feat, y, a_raw, W_gate, b_gate, W_B, b_B, W_C, b_C,
        W_sig, b_sig, W_R, b_R, p0, out);
    phase3_kernel<<<1, 32>>>(out);
}

// round 9
// speedup vs baseline: 3.3573x; 1.0161x over previous
#include <cuda_runtime.h>
#include <math.h>

#define BB 32
#define TT 2048
#define DF 128
#define NN 16
#define DY 8
#define RECSZ 256
#define NTOK 32
#define NCHUNK 64                 // TT / NTOK
#define LOG2PI 1.8378770664093455f

__device__ float g_rec[(size_t)BB * TT * RECSZ];   // zero-init; pad [192,256) never written
__device__ float g_llsum[BB];
__device__ int   g_flag[BB * NCHUNK];              // memset to 0 each launch

typedef unsigned long long ull;

__device__ __forceinline__ ull pk2(float a, float b) {
    ull r; asm("mov.b64 %0, {%1,%2};" : "=l"(r) : "f"(a), "f"(b)); return r;
}
__device__ __forceinline__ float sum2(ull v) {
    float a, b; asm("mov.b64 {%0,%1}, %2;" : "=f"(a), "=f"(b) : "l"(v)); return a + b;
}
__device__ __forceinline__ ull ffma2(ull a, ull b, ull c) {
    ull d; asm("fma.rn.f32x2 %0, %1, %2, %3;" : "=l"(d) : "l"(a), "l"(b), "l"(c)); return d;
}
__device__ __forceinline__ ull fadd2(ull a, ull b) {
    ull d; asm("add.rn.f32x2 %0, %1, %2;" : "=l"(d) : "l"(a), "l"(b)); return d;
}
__device__ __forceinline__ float frcp(float x) {
    float r; asm("rcp.approx.f32 %0, %1;" : "=f"(r) : "f"(x)); return r;
}
__device__ __forceinline__ void cp16(float* s, const void* g) {
    unsigned a = (unsigned)__cvta_generic_to_shared(s);
    asm volatile("cp.async.cg.shared.global [%0], [%1], 16;" :: "r"(a), "l"(g));
}
__device__ __forceinline__ void cpcommit() { asm volatile("cp.async.commit_group;"); }
template<int N> __device__ __forceinline__ void cpwait() {
    asm volatile("cp.async.wait_group %0;" :: "n"(N));
}

__device__ __forceinline__ float sp(float x) {
    return fmaxf(x, 0.f) + log1pf(expf(-fabsf(x)));
}
__device__ __forceinline__ float phik(float z, float k) {
    float kz = k * z;
    if (fabsf(kz) < 1e-4f) return 1.f + 0.5f * kz;
    return expm1f(kz) / kz;
}

__device__ __forceinline__ ull dot64(const float* __restrict__ row, const ull* xr2) {
    ull a0 = 0, a1 = 0, a2 = 0, a3 = 0;
#pragma unroll
    for (int k = 0; k < 8; k++) {
        ulonglong2 w0 = *(const ulonglong2*)(row + 8 * k);
        ulonglong2 w1 = *(const ulonglong2*)(row + 8 * k + 4);
        a0 = ffma2(w0.x, xr2[4 * k + 0], a0);
        a1 = ffma2(w0.y, xr2[4 * k + 1], a1);
        a2 = ffma2(w1.x, xr2[4 * k + 2], a2);
        a3 = ffma2(w1.y, xr2[4 * k + 3], a3);
    }
    return fadd2(fadd2(a0, a2), fadd2(a1, a3));
}

// producer dynamic smem layout (float offsets)
#define SM_SX    0
#define SM_SPART 4224
#define SM_SSML  12416
#define SM_W0    14080
#define SM_W1    30464
#define SM_TOT   46848
#define SM_BYTES (SM_TOT * 4)

__device__ __forceinline__ void stageW512(const float* src, float* dst, int tid) {
    const float4* s4 = (const float4*)src;
#pragma unroll
    for (int i = 0; i < 8; i++) {
        int idx = tid + i * 512;
        cp16(dst + idx * 4, s4 + idx);
    }
}

// ---------------------------------------------------------------------------
// Fused kernel: blocks 0..31 = scanners (1 warp), blocks 32.. = producers.
// ---------------------------------------------------------------------------
__global__ __launch_bounds__(512, 1) void fused_kernel(
    const float* __restrict__ x, const float* __restrict__ y,
    const float* __restrict__ a_raw,
    const float* __restrict__ Wg, const float* __restrict__ bg,
    const float* __restrict__ WB, const float* __restrict__ bB,
    const float* __restrict__ WC, const float* __restrict__ bC,
    const float* __restrict__ Ws, const float* __restrict__ bs,
    const float* __restrict__ WR, const float* __restrict__ bR,
    const float* __restrict__ p0, float* __restrict__ out)
{
    // ---- scanner static smem ----
    __shared__ __align__(16) float rec2[2][RECSZ];
    __shared__ __align__(16) float sP[320], sCP[160], sCPT[192];
    __shared__ __align__(16) float sS[72], se[8], hh[16], hp[16], yps[8], Sd[8];

    if (blockIdx.x >= BB) {
        // ================= PRODUCER =================
        extern __shared__ float dsm[];
        float* sx    = dsm + SM_SX;
        float* spart = dsm + SM_SPART;
        float* ssml  = dsm + SM_SSML;
        float* sW0   = dsm + SM_W0;
        float* sW1   = dsm + SM_W1;

        const int tid = threadIdx.x;
        const int warp = tid >> 5, l = tid & 31;
        const int wf = warp & 7, half = warp >> 3;
        const int co = half * 64;
        const int p = blockIdx.x - BB;
        const int batch = p & 31, tchunk = p >> 5;         // time-major order
        const size_t base = (size_t)batch * TT + (size_t)tchunk * NTOK;

        stageW512(WB, sW0, tid);
        cpcommit();

        for (int k = tid; k < NTOK * DF; k += 512) {
            int tok = k >> 7, g = k & 127;
            sx[tok * 132 + g] = x[(base + tok) * DF + g];
        }
        __syncthreads();

        ull xr2[32];
#pragma unroll
        for (int k = 0; k < 16; k++) {
            ulonglong2 v = *(const ulonglong2*)(sx + l * 132 + co + 4 * k);
            xr2[2 * k] = v.x; xr2[2 * k + 1] = v.y;
        }

#pragma unroll
        for (int rr = 0; rr < 4; rr++) {
            int r = wf + 8 * rr;
            if (r < 25) {
                const float* Wrow; float bias;
                if (r == 0)      { Wrow = Wg;                 bias = bg[0]; }
                else if (r < 17) { Wrow = Ws + (r - 1) * DF;  bias = bs[r - 1]; }
                else             { Wrow = WR + (r - 17) * DF; bias = bR[r - 17]; }
                float v = sum2(dot64(Wrow + co, xr2));
                if (half == 0) v += bias;
                ssml[r * 66 + half * 33 + l] = v;
            }
        }

        for (int n = 0; n < NN; n++) {
            float* cur = (n & 1) ? sW1 : sW0;
            float* nxt = (n & 1) ? sW0 : sW1;
            __syncthreads();
            if (n < 15) { stageW512(WB + (size_t)(n + 1) * 16384, nxt, tid); cpcommit(); cpwait<1>(); }
            else        { cpwait<0>(); }
            __syncthreads();

            ull accn2 = 0;
            float bacc = 0.f;
#pragma unroll 4
            for (int fi = 0; fi < 16; fi++) {
                int f = wf + 8 * fi;
                ull rp = dot64(cur + f * 128 + co, xr2);
                float xf = sx[l * 132 + f];
                accn2 = ffma2(pk2(xf, xf), rp, accn2);
                if (half == 0) bacc += xf * bB[n * 128 + f];
            }
            spart[warp * 512 + n * 32 + l] = sum2(accn2) + bacc;
        }
        __syncthreads();

        stageW512(WC, sW0, tid);
        cpcommit();

        {
            int tok = tid & 31, n = tid >> 5;
            float hsum = 0.f;
#pragma unroll
            for (int w2 = 0; w2 < 16; w2++) hsum += spart[w2 * 512 + n * 32 + tok];
            float gate = ssml[tok] + ssml[33 + tok];
            float Delta = sp(gate) + 1e-6f;
            Delta = fminf(fmaxf(Delta, 1e-3f), 1.0f);
            float a = -(sp(a_raw[n]) + 1e-6f);
            float z = fminf(fmaxf(Delta * a, -20.f), 20.f);
            float ez  = expf(z);
            float gam = phik(z, 1.f);
            float rho = phik(z, 2.f);
            float sg = sp(ssml[(1 + n) * 66 + tok] + ssml[(1 + n) * 66 + 33 + tok]) + 1e-6f + 1e-3f;
            size_t rb = (base + tok) * RECSZ;
            g_rec[rb + n]      = ez;
            g_rec[rb + 16 + n] = gam * Delta * hsum;
            g_rec[rb + 32 + n] = sg * sg * rho * Delta;
            if (n < DY) {
                g_rec[rb + 176 + n] = sp(ssml[(17 + n) * 66 + tok] + ssml[(17 + n) * 66 + 33 + tok])
                                      + 1e-6f + 1e-4f;
                g_rec[rb + 184 + n] = y[(base + tok) * DY + n];
            }
        }
        cpwait<0>();
        __syncthreads();

#pragma unroll 4
        for (int jj = 0; jj < 16; jj++) {
            int j = wf * 16 + jj;
            spart[j * 64 + half * 32 + l] = sum2(dot64(sW0 + j * 128 + co, xr2));
        }
        __syncthreads();

        for (int idx = tid; idx < 1024; idx += 512) {
            int tok = idx & 31, j4 = (idx >> 5) * 4;
            float4 v;
            v.x = spart[(j4 + 0) * 64 + tok] + spart[(j4 + 0) * 64 + 32 + tok] + bC[j4 + 0];
            v.y = spart[(j4 + 1) * 64 + tok] + spart[(j4 + 1) * 64 + 32 + tok] + bC[j4 + 1];
            v.z = spart[(j4 + 2) * 64 + tok] + spart[(j4 + 2) * 64 + 32 + tok] + bC[j4 + 2];
            v.w = spart[(j4 + 3) * 64 + tok] + spart[(j4 + 3) * 64 + 32 + tok] + bC[j4 + 3];
            *(float4*)(&g_rec[(base + tok) * RECSZ + 48 + j4]) = v;
        }

        // publish chunk
        __threadfence();
        __syncthreads();
        if (tid == 0) atomicExch(&g_flag[batch * NCHUNK + tchunk], 1);
        return;
    }

    // ================= SCANNER (1 warp per batch) =================
    const int b = blockIdx.x, l = threadIdx.x;
    if (l >= 32) return;
    const unsigned FULL = 0xffffffffu;

    const int i2 = l >> 1, jb = (l & 1) * 8;
    const int d4 = l >> 2, j04 = (l & 3) * 4;

#pragma unroll
    for (int u = 0; u < 8; u++)
        sP[i2 * 20 + jb + u] = (i2 == jb + u) ? fabsf(p0[i2]) : 0.f;
    if (l < 16) hh[l] = 0.f;
    float ll_s = 0.f, ll_c = 0.f;                // lane 24

    // wait chunk 0, stage record 0 into buffer 0
    {
        volatile int* f = &g_flag[b * NCHUNK];
        while (*f == 0) __nanosleep(64);
    }
    __threadfence();
    const float* RB = g_rec + (size_t)b * TT * RECSZ;
    {
        float4 a0 = *(const float4*)(RB + l * 8);
        float4 a1 = *(const float4*)(RB + l * 8 + 4);
        *(float4*)(&rec2[0][l * 8])     = a0;
        *(float4*)(&rec2[0][l * 8 + 4]) = a1;
    }

    float* om = out;
    float* ov = out + (size_t)BB * TT * DY;

    for (int t = 0; t < TT; t++) {
        __syncwarp(FULL);           // rec buffer, sP, hh from prev iter visible
        const float* rec = rec2[t & 1];
        float* rnx = rec2[(t + 1) & 1];

        // prefetch next record (LDG issued early, STS at iter bottom)
        float4 pfa, pfb;
        {
            int tn = (t + 1 < TT) ? t + 1 : t;
            if (tn > t && (tn & 31) == 0) {
                volatile int* f = &g_flag[b * NCHUNK + (tn >> 5)];
                while (*f == 0) __nanosleep(64);
                __threadfence();
            }
            const float* nx = RB + (size_t)tn * RECSZ;
            pfa = *(const float4*)(nx + l * 8);
            pfb = *(const float4*)(nx + l * 8 + 4);
        }

        // ---- stage A: hp (lanes<16) + CP ----
        if (l < 16) hp[l] = rec[l] * hh[l] + rec[16 + l];
        {
            float4 ez0 = *(const float4*)&rec[0];
            float4 ez1 = *(const float4*)&rec[4];
            float4 ez2 = *(const float4*)&rec[8];
            float4 ez3 = *(const float4*)&rec[12];
            float ezl[16] = {ez0.x,ez0.y,ez0.z,ez0.w, ez1.x,ez1.y,ez1.z,ez1.w,
                             ez2.x,ez2.y,ez2.z,ez2.w, ez3.x,ez3.y,ez3.z,ez3.w};
            const float* Crow = rec + 48 + d4 * 16;
            float4 ca = *(const float4*)(Crow);
            float4 cb = *(const float4*)(Crow + 4);
            float4 cc = *(const float4*)(Crow + 8);
            float4 cd = *(const float4*)(Crow + 12);
            float C[16] = {ca.x,ca.y,ca.z,ca.w, cb.x,cb.y,cb.z,cb.w,
                           cc.x,cc.y,cc.z,cc.w, cd.x,cd.y,cd.z,cd.w};
            float4 qv  = *(const float4*)&rec[32 + j04];
            float4 ezj = *(const float4*)&rec[j04];
            float aA0=0.f,aA1=0.f,aA2=0.f,aA3=0.f;
            float aB0=0.f,aB1=0.f,aB2=0.f,aB3=0.f;
#pragma unroll
            for (int n = 0; n < 16; n += 2) {
                float chA = C[n] * ezl[n];
                float chB = C[n + 1] * ezl[n + 1];
                float4 pA = *(const float4*)&sP[n * 20 + j04];
                float4 pB = *(const float4*)&sP[(n + 1) * 20 + j04];
                aA0 += chA * pA.x; aA1 += chA * pA.y; aA2 += chA * pA.z; aA3 += chA * pA.w;
                aB0 += chB * pB.x; aB1 += chB * pB.y; aB2 += chB * pB.z; aB3 += chB * pB.w;
            }
            float4 cp;
            cp.x = ezj.x * (aA0 + aB0) + C[j04 + 0] * qv.x;
            cp.y = ezj.y * (aA1 + aB1) + C[j04 + 1] * qv.y;
            cp.z = ezj.z * (aA2 + aB2) + C[j04 + 2] * qv.z;
            cp.w = ezj.w * (aA3 + aB3) + C[j04 + 3] * qv.w;
            *(float4*)&sCP[d4 * 20 + j04] = cp;
            sCPT[(j04 + 0) * 12 + d4] = cp.x;
            sCPT[(j04 + 1) * 12 + d4] = cp.y;
            sCPT[(j04 + 2) * 12 + d4] = cp.z;
            sCPT[(j04 + 3) * 12 + d4] = cp.w;
        }
        __syncwarp(FULL);

        // ---- stage B: S (2 per lane) + y_pred/e (lanes 24..31) ----
        {
            int d = d4, q0 = (l & 3) * 2;
            ulonglong2 g0 = *(const ulonglong2*)&sCP[d * 20];
            ulonglong2 g1 = *(const ulonglong2*)&sCP[d * 20 + 4];
            ulonglong2 g2 = *(const ulonglong2*)&sCP[d * 20 + 8];
            ulonglong2 g3 = *(const ulonglong2*)&sCP[d * 20 + 12];
#pragma unroll
            for (int qq = 0; qq < 2; qq++) {
                int q = q0 + qq;
                ulonglong2 c0 = *(const ulonglong2*)&rec[48 + q * 16];
                ulonglong2 c1 = *(const ulonglong2*)&rec[48 + q * 16 + 4];
                ulonglong2 c2 = *(const ulonglong2*)&rec[48 + q * 16 + 8];
                ulonglong2 c3 = *(const ulonglong2*)&rec[48 + q * 16 + 12];
                ull x0 = ffma2(g0.x, c0.x, ffma2(g0.y, c0.y, 0));
                ull x1 = ffma2(g1.x, c1.x, ffma2(g1.y, c1.y, 0));
                ull x2 = ffma2(g2.x, c2.x, ffma2(g2.y, c2.y, 0));
                ull x3 = ffma2(g3.x, c3.x, ffma2(g3.y, c3.y, 0));
                float s = sum2(fadd2(fadd2(x0, x1), fadd2(x2, x3)));
                if (d == q) { s += rec[176 + d]; Sd[d] = s; }
                sS[d * 9 + q] = s;
            }
            if (l >= 24) {
                int dd = l - 24;
                float yp = 0.f;
#pragma unroll
                for (int n = 0; n < 16; n++) yp += rec[48 + dd * 16 + n] * hp[n];
                yps[dd] = yp;
                se[dd] = rec[184 + dd] - yp;
            }
        }
        __syncwarp(FULL);

        // ---- stage C: 2x2 block Gauss-Jordan on [S | CP | e], lane = column ----
        float r[8];
        if (l < 8) {
#pragma unroll
            for (int d = 0; d < 8; d++) r[d] = sS[d * 9 + l];
        } else if (l < 24) {
            int m = l - 8;
#pragma unroll
            for (int d = 0; d < 8; d++) r[d] = sCP[d * 20 + m];
        } else if (l == 24) {
#pragma unroll
            for (int d = 0; d < 8; d++) r[d] = se[d];
        } else {
#pragma unroll
            for (int d = 0; d < 8; d++) r[d] = 0.f;
        }
        float pprod = 1.f;
#pragma unroll
        for (int k = 0; k < 4; k++) {
            const int p0i = 2 * k, p1i = 2 * k + 1;
            float r0 = r[p0i], r1 = r[p1i];
            float pa = __shfl_sync(FULL, r0, p0i);   // A[p0][p0]
            float pc = __shfl_sync(FULL, r1, p0i);   // A[p1][p0]
            float pb = __shfl_sync(FULL, r0, p1i);   // A[p0][p1]
            float pd = __shfl_sync(FULL, r1, p1i);   // A[p1][p1]
            float det = pa * pd - pb * pc;
            pprod *= det;
            float rdet = frcp(det);
            float n0 = rdet * (pd * r0 - pb * r1);
            float n1 = rdet * (pa * r1 - pc * r0);
#pragma unroll
            for (int i = 0; i < 8; i++) {
                if (i == p0i || i == p1i) continue;
                float m0 = __shfl_sync(FULL, r[i], p0i);
                float m1 = __shfl_sync(FULL, r[i], p1i);
                r[i] -= m0 * n0 + m1 * n1;
            }
            r[p0i] = n0; r[p1i] = n1;
        }
        // lanes 8..23 now hold K'^T columns in r; lane 24 holds v.

        // ---- h_new directly on lanes 8..23 (no sKT round-trip) ----
        if (l >= 8 && l < 24) {
            int n = l - 8;
            ulonglong2 e0 = *(const ulonglong2*)&se[0];
            ulonglong2 e1 = *(const ulonglong2*)&se[4];
            ull acc = ffma2(pk2(r[0], r[1]), e0.x,
                      ffma2(pk2(r[2], r[3]), e0.y,
                      ffma2(pk2(r[4], r[5]), e1.x,
                      ffma2(pk2(r[6], r[7]), e1.y, 0))));
            hh[n] = hp[n] + sum2(acc);
        }
        if (l == 24) {
            float quad = 0.f;
#pragma unroll
            for (int d = 0; d < 8; d++) quad += se[d] * r[d];
            float ll = -0.5f * (logf(pprod) + quad + (float)DY * LOG2PI);
            float yk = ll - ll_c, tk = ll_s + yk;
            ll_c = (tk - ll_s) - yk; ll_s = tk;
        }

        // ---- P_new: K' column i2 fetched via shfl from lane 8+i2 ----
        {
            float m0 = __shfl_sync(FULL, r[0], 8 + i2);
            float m1 = __shfl_sync(FULL, r[1], 8 + i2);
            float m2 = __shfl_sync(FULL, r[2], 8 + i2);
            float m3 = __shfl_sync(FULL, r[3], 8 + i2);
            float m4 = __shfl_sync(FULL, r[4], 8 + i2);
            float m5 = __shfl_sync(FULL, r[5], 8 + i2);
            float m6 = __shfl_sync(FULL, r[6], 8 + i2);
            float m7 = __shfl_sync(FULL, r[7], 8 + i2);
            ull K0 = pk2(m0, m1), K1 = pk2(m2, m3);
            ull K2 = pk2(m4, m5), K3 = pk2(m6, m7);
            float ezi = rec[i2];
            float qi  = rec[32 + i2];
            float4 ej0 = *(const float4*)&rec[jb];
            float4 ej1 = *(const float4*)&rec[jb + 4];
            float ej[8] = {ej0.x,ej0.y,ej0.z,ej0.w, ej1.x,ej1.y,ej1.z,ej1.w};
            float4 pav = *(const float4*)&sP[i2 * 20 + jb];
            float4 pbv = *(const float4*)&sP[i2 * 20 + jb + 4];
            float pv[8] = {pav.x,pav.y,pav.z,pav.w, pbv.x,pbv.y,pbv.z,pbv.w};
            float o[8];
#pragma unroll
            for (int u = 0; u < 8; u++) {
                int j = jb + u;
                ulonglong2 c0 = *(const ulonglong2*)&sCPT[j * 12];
                ulonglong2 c1 = *(const ulonglong2*)&sCPT[j * 12 + 4];
                ull acc = ffma2(K0, c0.x, ffma2(K1, c0.y,
                          ffma2(K2, c1.x, ffma2(K3, c1.y, 0))));
                o[u] = ezi * ej[u] * pv[u] - sum2(acc) + ((i2 == j) ? qi : 0.f);
            }
            *(float4*)&sP[i2 * 20 + jb]     = make_float4(o[0], o[1], o[2], o[3]);
            *(float4*)&sP[i2 * 20 + jb + 4] = make_float4(o[4], o[5], o[6], o[7]);
        }
        if (l < DY) {
            size_t o = ((size_t)b * TT + t) * DY + l;
            om[o] = yps[l];
            ov[o] = Sd[l];
        }
        // stage next record into the other buffer (visible after loop-top sync)
        *(float4*)(&rnx[l * 8])     = pfa;
        *(float4*)(&rnx[l * 8 + 4]) = pfb;
    }
    if (l == 24) g_llsum[b] = ll_s;
}

__global__ void phase3_kernel(float* __restrict__ out) {
    float v = g_llsum[threadIdx.x];
#pragma unroll
    for (int o = 16; o > 0; o >>= 1) v += __shfl_down_sync(0xffffffffu, v, o);
    if (threadIdx.x == 0) {
        size_t off = (size_t)2 * BB * TT * DY;
        out[off]     = -v / (float)BB;
        out[off + 1] =  v / (float)(BB * TT);
    }
}

extern "C" void kernel_launch(void* const* d_in, const int* in_sizes, int n_in,
                              void* d_out, int out_size) {
    const float* x_feat = (const float*)d_in[0];
    const float* y      = (const float*)d_in[1];
    const float* a_raw  = (const float*)d_in[2];
    const float* W_gate = (const float*)d_in[3];
    const float* b_gate = (const float*)d_in[4];
    const float* W_B    = (const float*)d_in[5];
    const float* b_B    = (const float*)d_in[6];
    const float* W_C    = (const float*)d_in[7];
    const float* b_C    = (const float*)d_in[8];
    const float* W_sig  = (const float*)d_in[9];
    const float* b_sig  = (const float*)d_in[10];
    const float* W_R    = (const float*)d_in[11];
    const float* b_R    = (const float*)d_in[12];
    const float* p0     = (const float*)d_in[13];
    float* out = (float*)d_out;

    void* flag_ptr = nullptr;
    cudaGetSymbolAddress(&flag_ptr, g_flag);
    cudaMemsetAsync(flag_ptr, 0, BB * NCHUNK * sizeof(int), 0);

    cudaFuncSetAttribute(fused_kernel,
                         cudaFuncAttributeMaxDynamicSharedMemorySize, SM_BYTES);
    fused_kernel<<<BB + (BB * TT) / NTOK, 512, SM_BYTES>>>(
        x_feat, y, a_raw, W_gate, b_gate, W_B, b_B, W_C, b_C,
        W_sig, b_sig, W_R, b_R, p0, out);
    phase3_kernel<<<1, 32>>>(out);
}